// round 1
// baseline (speedup 1.0000x reference)
#include <cuda_runtime.h>
#include <math.h>

#define SEQ   2048
#define NB    4
#define NH    8
#define HD    128
#define ROWS  (NB*SEQ)          // 8192

// ---------------- scratch (static device allocations are allowed) ----------
__device__ float g_xn[ROWS*128];
__device__ float g_q[NB*NH*SEQ*HD];
__device__ float g_k[NB*NH*SEQ*HD];
__device__ float g_v[NB*NH*SEQ*HD];
__device__ float g_o[NB*NH*SEQ*HD];

// ---------------- 1. LayerNorm: one warp per 128-elem row ------------------
__global__ void ln_kernel(const float* __restrict__ x,
                          const float* __restrict__ gamma,
                          const float* __restrict__ beta) {
    int row  = blockIdx.x * 8 + (threadIdx.x >> 5);
    int lane = threadIdx.x & 31;
    float4 v = ((const float4*)(x + (size_t)row * 128))[lane];
    float s  = v.x + v.y + v.z + v.w;
    float s2 = v.x*v.x + v.y*v.y + v.z*v.z + v.w*v.w;
#pragma unroll
    for (int m = 16; m; m >>= 1) {
        s  += __shfl_xor_sync(0xffffffffu, s,  m);
        s2 += __shfl_xor_sync(0xffffffffu, s2, m);
    }
    float mean = s * (1.f/128.f);
    float var  = s2 * (1.f/128.f) - mean*mean;
    float rs   = rsqrtf(var + 1e-5f);
    float4 g = ((const float4*)gamma)[lane];
    float4 b = ((const float4*)beta)[lane];
    float4 o;
    o.x = (v.x-mean)*rs*g.x + b.x;
    o.y = (v.y-mean)*rs*g.y + b.y;
    o.z = (v.z-mean)*rs*g.z + b.z;
    o.w = (v.w-mean)*rs*g.w + b.w;
    ((float4*)(g_xn + (size_t)row*128))[lane] = o;
}

// ---------------- 2. QKV GEMM: [8192,128] @ W^T[128,3072] ------------------
// 64x64 tile, 256 threads, 4x4 per thread. Epilogue scatters to head-major
// q/k/v layout [b*8+h][n][d].
__global__ __launch_bounds__(256, 2) void qkv_kernel(const float* __restrict__ w) {
    extern __shared__ float sm[];
    float* As = sm;              // [128][68]  (k-major, padded)
    float* Bs = sm + 128*68;     // [128][68]
    int tid = threadIdx.x;
    int n0 = blockIdx.x * 64, m0 = blockIdx.y * 64;
    for (int idx = tid; idx < 64*128; idx += 256) {
        int r = idx >> 7, c = idx & 127;
        As[c*68 + r] = g_xn[(m0 + r)*128 + c];
        Bs[c*68 + r] = w[(n0 + r)*128 + c];
    }
    __syncthreads();
    int ty = tid >> 4, tx = tid & 15;
    float acc[4][4] = {};
#pragma unroll 8
    for (int kk = 0; kk < 128; kk++) {
        float4 a = *(const float4*)&As[kk*68 + 4*ty];
        float4 b = *(const float4*)&Bs[kk*68 + 4*tx];
        float av[4] = {a.x, a.y, a.z, a.w};
        float bv[4] = {b.x, b.y, b.z, b.w};
#pragma unroll
        for (int i = 0; i < 4; i++)
#pragma unroll
            for (int j = 0; j < 4; j++) acc[i][j] += av[i] * bv[j];
    }
#pragma unroll
    for (int i = 0; i < 4; i++) {
        int m = m0 + 4*ty + i;
        int b_ = m >> 11, n = m & 2047;
#pragma unroll
        for (int j = 0; j < 4; j++) {
            int e = n0 + 4*tx + j;
            int part = e >> 10, r = e & 1023, h = r >> 7, d = r & 127;
            float* dst = (part == 0) ? g_q : (part == 1 ? g_k : g_v);
            dst[(((b_ << 3) + h)*2048 + n)*128 + d] = acc[i][j];
        }
    }
}

// ---------------- 3. RoPE: all heads, positions 0..2046 only ---------------
__global__ void rope_kernel() {
    int n  = blockIdx.x;          // 0..2046
    int bh = blockIdx.y;          // 0..31
    int j  = threadIdx.x;         // 0..63 (pair index)
    // correctly-rounded inv_freq; exponent 2j/128 exact in binary
    float inv = (float)pow(10000.0, -((double)(2*j) / 128.0));
    float ang = (float)n * inv;
    float s, c;
    sincosf(ang, &s, &c);
    int base = (bh*2048 + n)*128 + 2*j;
    float q0 = g_q[base], q1 = g_q[base+1];
    g_q[base]   = q0*c - q1*s;
    g_q[base+1] = q1*c + q0*s;
    float k0 = g_k[base], k1 = g_k[base+1];
    g_k[base]   = k0*c - k1*s;
    g_k[base+1] = k1*c + k0*s;
}

// ---------------- 4. Flash attention, fp32, BM=BN=64 -----------------------
// 256 threads (16x16). S micro-tile 4x4, O micro-tile 4x8. Online softmax via
// 16-lane shuffle reductions. K streamed in two 64-wide d-chunks so smem
// (Qs 34.8K + Ks 17.4K + Vs 32K + Ps 17.4K = 100K) allows 2 CTAs/SM.
__global__ __launch_bounds__(256, 2) void attn_kernel() {
    extern __shared__ float sm[];
    float* Qs = sm;                  // [128][68]
    float* Ks = Qs + 128*68;         // [64][68]
    float* Vs = Ks + 64*68;          // [64][128]
    float* Ps = Vs + 64*128;         // [64][68]
    int tid = threadIdx.x;
    int bh  = blockIdx.y;
    int m0  = blockIdx.x * 64;
    const float* Q = g_q + (size_t)bh*SEQ*128;
    const float* K = g_k + (size_t)bh*SEQ*128;
    const float* V = g_v + (size_t)bh*SEQ*128;

    for (int idx = tid; idx < 64*128; idx += 256) {
        int r = idx >> 7, c = idx & 127;
        Qs[c*68 + r] = Q[(m0 + r)*128 + c];
    }
    int ty = tid >> 4, tx = tid & 15;
    float o[4][8];
    float mprev[4], l[4];
#pragma unroll
    for (int i = 0; i < 4; i++) {
        mprev[i] = -INFINITY; l[i] = 0.f;
#pragma unroll
        for (int c = 0; c < 8; c++) o[i][c] = 0.f;
    }
    const float scale = 0.08838834764831845f;   // 128^-0.5

    for (int t = 0; t < 32; t++) {
        int j0 = t * 64;
        __syncthreads();   // protect Vs/Ks/Ps from previous iteration readers
        for (int idx = tid; idx < 64*128; idx += 256) {
            int r = idx >> 7, c = idx & 127;
            Vs[idx] = V[(j0 + r)*128 + c];
        }
        for (int idx = tid; idx < 64*64; idx += 256) {
            int r = idx >> 6, c = idx & 63;
            Ks[c*68 + r] = K[(j0 + r)*128 + c];
        }
        __syncthreads();
        float acc[4][4] = {};
#pragma unroll 8
        for (int kk = 0; kk < 64; kk++) {
            float4 a = *(const float4*)&Qs[kk*68 + 4*ty];
            float4 b = *(const float4*)&Ks[kk*68 + 4*tx];
            float av[4] = {a.x,a.y,a.z,a.w}, bv[4] = {b.x,b.y,b.z,b.w};
#pragma unroll
            for (int i = 0; i < 4; i++)
#pragma unroll
                for (int j = 0; j < 4; j++) acc[i][j] += av[i]*bv[j];
        }
        __syncthreads();
        for (int idx = tid; idx < 64*64; idx += 256) {
            int r = idx >> 6, c = idx & 63;
            Ks[c*68 + r] = K[(j0 + r)*128 + 64 + c];
        }
        __syncthreads();
#pragma unroll 8
        for (int kk = 0; kk < 64; kk++) {
            float4 a = *(const float4*)&Qs[(64 + kk)*68 + 4*ty];
            float4 b = *(const float4*)&Ks[kk*68 + 4*tx];
            float av[4] = {a.x,a.y,a.z,a.w}, bv[4] = {b.x,b.y,b.z,b.w};
#pragma unroll
            for (int i = 0; i < 4; i++)
#pragma unroll
                for (int j = 0; j < 4; j++) acc[i][j] += av[i]*bv[j];
        }
        // ---- online softmax over this 64-key tile ----
#pragma unroll
        for (int i = 0; i < 4; i++) {
#pragma unroll
            for (int j = 0; j < 4; j++) acc[i][j] *= scale;
            float mx = fmaxf(fmaxf(acc[i][0], acc[i][1]), fmaxf(acc[i][2], acc[i][3]));
#pragma unroll
            for (int msk = 8; msk; msk >>= 1)
                mx = fmaxf(mx, __shfl_xor_sync(0xffffffffu, mx, msk));
            float mnew  = fmaxf(mprev[i], mx);
            float alpha = expf(mprev[i] - mnew);
            float ps = 0.f;
#pragma unroll
            for (int j = 0; j < 4; j++) {
                acc[i][j] = expf(acc[i][j] - mnew);
                ps += acc[i][j];
            }
#pragma unroll
            for (int msk = 8; msk; msk >>= 1)
                ps += __shfl_xor_sync(0xffffffffu, ps, msk);
            l[i] = l[i]*alpha + ps;
            mprev[i] = mnew;
#pragma unroll
            for (int c = 0; c < 8; c++) o[i][c] *= alpha;
            *(float4*)&Ps[(4*ty + i)*68 + 4*tx] =
                make_float4(acc[i][0], acc[i][1], acc[i][2], acc[i][3]);
        }
        __syncthreads();
        // ---- O += P @ V ----
#pragma unroll 4
        for (int j = 0; j < 64; j++) {
            float p0 = Ps[(4*ty + 0)*68 + j];
            float p1 = Ps[(4*ty + 1)*68 + j];
            float p2 = Ps[(4*ty + 2)*68 + j];
            float p3 = Ps[(4*ty + 3)*68 + j];
            float4 v0 = *(const float4*)&Vs[j*128 + 8*tx];
            float4 v1 = *(const float4*)&Vs[j*128 + 8*tx + 4];
            float vv[8] = {v0.x,v0.y,v0.z,v0.w,v1.x,v1.y,v1.z,v1.w};
#pragma unroll
            for (int c = 0; c < 8; c++) {
                o[0][c] += p0*vv[c];
                o[1][c] += p1*vv[c];
                o[2][c] += p2*vv[c];
                o[3][c] += p3*vv[c];
            }
        }
    }
#pragma unroll
    for (int i = 0; i < 4; i++) {
        float inv = 1.f / l[i];
        int m = m0 + 4*ty + i;
        float* dst = g_o + ((size_t)bh*2048 + m)*128 + 8*tx;
        *(float4*)&dst[0] = make_float4(o[i][0]*inv, o[i][1]*inv, o[i][2]*inv, o[i][3]*inv);
        *(float4*)&dst[4] = make_float4(o[i][4]*inv, o[i][5]*inv, o[i][6]*inv, o[i][7]*inv);
    }
}

// ---------------- 5. Out projection: [8192,1024] @ w_out^T + b ------------
__global__ __launch_bounds__(256, 2) void outproj_kernel(const float* __restrict__ w_out,
                                                         const float* __restrict__ b_out,
                                                         float* __restrict__ out) {
    __shared__ float As[32*68];    // [32][68]  k-major A tile (transposed read)
    __shared__ float Bs[32*132];   // [32][132] k-major W tile
    int tid = threadIdx.x;
    int ty = tid >> 4, tx = tid & 15;
    int m0 = blockIdx.x * 64;
    float acc[4][8] = {};
    for (int k0 = 0; k0 < 1024; k0 += 32) {
        __syncthreads();
        for (int idx = tid; idx < 64*32; idx += 256) {
            int r = idx >> 5, kk = idx & 31;
            int m = m0 + r, b = m >> 11, n = m & 2047;
            int kg = k0 + kk, h = kg >> 7, d = kg & 127;
            As[kk*68 + r] = g_o[(((b << 3) + h)*2048 + n)*128 + d];
        }
        for (int idx = tid; idx < 128*32; idx += 256) {
            int c = idx >> 5, kk = idx & 31;
            Bs[kk*132 + c] = w_out[c*1024 + k0 + kk];
        }
        __syncthreads();
#pragma unroll 8
        for (int kk = 0; kk < 32; kk++) {
            float4 a  = *(const float4*)&As[kk*68 + 4*ty];
            float4 b0 = *(const float4*)&Bs[kk*132 + 8*tx];
            float4 b1 = *(const float4*)&Bs[kk*132 + 8*tx + 4];
            float av[4] = {a.x,a.y,a.z,a.w};
            float bv[8] = {b0.x,b0.y,b0.z,b0.w,b1.x,b1.y,b1.z,b1.w};
#pragma unroll
            for (int i = 0; i < 4; i++)
#pragma unroll
                for (int c = 0; c < 8; c++) acc[i][c] += av[i]*bv[c];
        }
    }
#pragma unroll
    for (int i = 0; i < 4; i++) {
        int m = m0 + 4*ty + i;
#pragma unroll
        for (int c = 0; c < 8; c++) {
            int cg = 8*tx + c;
            out[m*128 + cg] = acc[i][c] + b_out[cg];
        }
    }
}

// ---------------- launcher -------------------------------------------------
extern "C" void kernel_launch(void* const* d_in, const int* in_sizes, int n_in,
                              void* d_out, int out_size) {
    const float* x      = (const float*)d_in[0];
    const float* gamma  = (const float*)d_in[1];
    const float* beta   = (const float*)d_in[2];
    const float* w_qkv  = (const float*)d_in[3];
    const float* w_out  = (const float*)d_in[4];
    const float* b_out  = (const float*)d_in[5];
    float* out = (float*)d_out;

    ln_kernel<<<1024, 256>>>(x, gamma, beta);

    cudaFuncSetAttribute(qkv_kernel, cudaFuncAttributeMaxDynamicSharedMemorySize, 69632);
    qkv_kernel<<<dim3(48, 128), 256, 69632>>>(w_qkv);

    rope_kernel<<<dim3(2047, 32), 64>>>();

    cudaFuncSetAttribute(attn_kernel, cudaFuncAttributeMaxDynamicSharedMemorySize, 102400);
    attn_kernel<<<dim3(32, 32), 256, 102400>>>();

    outproj_kernel<<<128, 256>>>(w_out, b_out, out);
}

// round 2
// speedup vs baseline: 1.4581x; 1.4581x over previous
#include <cuda_runtime.h>
#include <math.h>

#define SEQ   2048
#define NB    4
#define NH    8
#define HD    128
#define ROWS  (NB*SEQ)          // 8192

// ---------------- scratch ----------------
__device__ float g_xn[ROWS*128];
__device__ float g_q[NB*NH*SEQ*HD];
__device__ float g_k[NB*NH*SEQ*HD];
__device__ float g_v[NB*NH*SEQ*HD];
__device__ float g_o[NB*NH*SEQ*HD];

// ---------------- 1. LayerNorm: one warp per 128-elem row ------------------
__global__ void ln_kernel(const float* __restrict__ x,
                          const float* __restrict__ gamma,
                          const float* __restrict__ beta) {
    int row  = blockIdx.x * 8 + (threadIdx.x >> 5);
    int lane = threadIdx.x & 31;
    float4 v = ((const float4*)(x + (size_t)row * 128))[lane];
    float s  = v.x + v.y + v.z + v.w;
    float s2 = v.x*v.x + v.y*v.y + v.z*v.z + v.w*v.w;
#pragma unroll
    for (int m = 16; m; m >>= 1) {
        s  += __shfl_xor_sync(0xffffffffu, s,  m);
        s2 += __shfl_xor_sync(0xffffffffu, s2, m);
    }
    float mean = s * (1.f/128.f);
    float var  = s2 * (1.f/128.f) - mean*mean;
    float rs   = rsqrtf(var + 1e-5f);
    float4 g = ((const float4*)gamma)[lane];
    float4 b = ((const float4*)beta)[lane];
    float4 o;
    o.x = (v.x-mean)*rs*g.x + b.x;
    o.y = (v.y-mean)*rs*g.y + b.y;
    o.z = (v.z-mean)*rs*g.z + b.z;
    o.w = (v.w-mean)*rs*g.w + b.w;
    ((float4*)(g_xn + (size_t)row*132 - (size_t)row*4))[lane] = o;   // plain row*128
}

// ---------------- 2. QKV GEMM: [8192,128] @ W^T -> 3x[b,h,n,d] -------------
// Tile 128x64, 256 threads, micro 8x4. K=128 resident.
__global__ __launch_bounds__(256, 1) void qkv_kernel(const float* __restrict__ w) {
    extern __shared__ float sm[];
    float* As = sm;              // [128 kk][132]  As[kk][m]
    float* Bs = sm + 128*132;    // [128 kk][68]   Bs[kk][n]
    int tid = threadIdx.x;
    int n0 = blockIdx.x * 64, m0 = blockIdx.y * 128;
    for (int idx = tid; idx < 128*128; idx += 256) {
        int d = idx & 127, m = idx >> 7;
        As[d*132 + m] = g_xn[(m0 + m)*128 + d];
    }
    for (int idx = tid; idx < 64*128; idx += 256) {
        int d = idx & 127, n = idx >> 7;
        Bs[d*68 + n] = w[(n0 + n)*128 + d];
    }
    __syncthreads();
    int ty = tid >> 4, tx = tid & 15;
    float acc[8][4] = {};
#pragma unroll 8
    for (int kk = 0; kk < 128; kk++) {
        const float* qp = &As[kk*132 + 8*ty];
        float4 a0 = *(const float4*)qp;
        float4 a1 = *(const float4*)(qp + 4);
        float4 b  = *(const float4*)&Bs[kk*68 + 4*tx];
        float av[8] = {a0.x,a0.y,a0.z,a0.w,a1.x,a1.y,a1.z,a1.w};
        float bv[4] = {b.x,b.y,b.z,b.w};
#pragma unroll
        for (int i = 0; i < 8; i++)
#pragma unroll
            for (int j = 0; j < 4; j++) acc[i][j] += av[i]*bv[j];
    }
#pragma unroll
    for (int i = 0; i < 8; i++) {
        int m = m0 + 8*ty + i;
        int b_ = m >> 11, n = m & 2047;
#pragma unroll
        for (int j = 0; j < 4; j++) {
            int e = n0 + 4*tx + j;
            int part = e >> 10, r = e & 1023, h = r >> 7, d = r & 127;
            float* dst = (part == 0) ? g_q : (part == 1 ? g_k : g_v);
            dst[(((b_ << 3) + h)*2048 + n)*128 + d] = acc[i][j];
        }
    }
}

// ---------------- 3. RoPE: all heads, positions 0..2046 only ---------------
__global__ void rope_kernel() {
    int n  = blockIdx.x;          // 0..2046
    int bh = blockIdx.y;          // 0..31
    int j  = threadIdx.x;         // 0..63
    float inv = (float)pow(10000.0, -((double)(2*j) / 128.0));
    float ang = (float)n * inv;
    float s, c;
    sincosf(ang, &s, &c);
    int base = (bh*2048 + n)*128 + 2*j;
    float q0 = g_q[base], q1 = g_q[base+1];
    g_q[base]   = q0*c - q1*s;
    g_q[base+1] = q1*c + q0*s;
    float k0 = g_k[base], k1 = g_k[base+1];
    g_k[base]   = k0*c - k1*s;
    g_k[base+1] = k1*c + k0*s;
}

// ---------------- 4. Flash attention fp32, BM=128 BN=64, 8x4 / 8x8 --------
// smem: Qs[128][132] (k-major, scale folded) + Ks[32][68] + Vs[32][132] + Ps[128][68]
__global__ __launch_bounds__(256, 1) void attn_kernel() {
    extern __shared__ float sm[];
    float* Qs = sm;                    // 128*132 = 16896
    float* Ks = Qs + 128*132;          // 32*68   = 2176
    float* Vs = Ks + 32*68;            // 32*132  = 4224
    float* Ps = Vs + 32*132;           // 128*68  = 8704
    int tid = threadIdx.x;
    int bh  = blockIdx.y;
    int m0  = blockIdx.x * 128;
    const float* Q = g_q + (size_t)bh*SEQ*128;
    const float* K = g_k + (size_t)bh*SEQ*128;
    const float* V = g_v + (size_t)bh*SEQ*128;
    const float scale = 0.08838834764831845f;

    // load Q tile k-major, fold scale
    for (int idx = tid; idx < 128*128; idx += 256) {
        int d = idx & 127, m = idx >> 7;
        Qs[d*132 + m] = Q[(m0 + m)*128 + d] * scale;
    }

    int ty = tid >> 4, tx = tid & 15;
    float o[8][8];
    float mprev[8], l[8];
#pragma unroll
    for (int i = 0; i < 8; i++) {
        mprev[i] = -INFINITY; l[i] = 0.f;
#pragma unroll
        for (int c = 0; c < 8; c++) o[i][c] = 0.f;
    }

    for (int t = 0; t < 32; t++) {
        int j0 = t * 64;
        float acc[8][4] = {};
        // ---- S = Qs @ K^T over 4 d-chunks of 32 ----
        for (int dc = 0; dc < 4; dc++) {
            __syncthreads();
            for (int idx = tid; idx < 32*64; idx += 256) {
                int kk = idx & 31, n = idx >> 5;
                Ks[kk*68 + n] = K[(j0 + n)*128 + dc*32 + kk];
            }
            __syncthreads();
#pragma unroll 8
            for (int kk = 0; kk < 32; kk++) {
                const float* qp = &Qs[(dc*32 + kk)*132 + 8*ty];
                float4 a0 = *(const float4*)qp;
                float4 a1 = *(const float4*)(qp + 4);
                float4 b  = *(const float4*)&Ks[kk*68 + 4*tx];
                float av[8] = {a0.x,a0.y,a0.z,a0.w,a1.x,a1.y,a1.z,a1.w};
                float bv[4] = {b.x,b.y,b.z,b.w};
#pragma unroll
                for (int i = 0; i < 8; i++)
#pragma unroll
                    for (int j = 0; j < 4; j++) acc[i][j] += av[i]*bv[j];
            }
        }
        // ---- online softmax over this 64-key tile ----
#pragma unroll
        for (int i = 0; i < 8; i++) {
            float mx = fmaxf(fmaxf(acc[i][0], acc[i][1]), fmaxf(acc[i][2], acc[i][3]));
#pragma unroll
            for (int msk = 8; msk; msk >>= 1)
                mx = fmaxf(mx, __shfl_xor_sync(0xffffffffu, mx, msk));
            float mnew  = fmaxf(mprev[i], mx);
            float alpha = __expf(mprev[i] - mnew);
            float ps = 0.f;
#pragma unroll
            for (int j = 0; j < 4; j++) {
                acc[i][j] = __expf(acc[i][j] - mnew);
                ps += acc[i][j];
            }
#pragma unroll
            for (int msk = 8; msk; msk >>= 1)
                ps += __shfl_xor_sync(0xffffffffu, ps, msk);
            l[i] = l[i]*alpha + ps;
            mprev[i] = mnew;
#pragma unroll
            for (int c = 0; c < 8; c++) o[i][c] *= alpha;
            *(float4*)&Ps[(8*ty + i)*68 + 4*tx] =
                make_float4(acc[i][0], acc[i][1], acc[i][2], acc[i][3]);
        }
        // ---- O += P @ V over 2 key sub-chunks of 32 ----
        for (int vc = 0; vc < 2; vc++) {
            __syncthreads();   // also publishes Ps writes
            for (int idx = tid; idx < 32*128; idx += 256) {
                int d = idx & 127, r = idx >> 7;
                Vs[r*132 + d] = V[(j0 + vc*32 + r)*128 + d];
            }
            __syncthreads();
#pragma unroll 4
            for (int j = 0; j < 32; j++) {
                float4 v0 = *(const float4*)&Vs[j*132 + 4*tx];
                float4 v1 = *(const float4*)&Vs[j*132 + 64 + 4*tx];
                float vv[8] = {v0.x,v0.y,v0.z,v0.w,v1.x,v1.y,v1.z,v1.w};
#pragma unroll
                for (int i = 0; i < 8; i++) {
                    float p = Ps[(8*ty + i)*68 + vc*32 + j];
#pragma unroll
                    for (int c = 0; c < 8; c++) o[i][c] += p*vv[c];
                }
            }
        }
    }
    // ---- epilogue: O columns are {4tx..4tx+3} and {64+4tx..64+4tx+3} ----
#pragma unroll
    for (int i = 0; i < 8; i++) {
        float inv = 1.f / l[i];
        int m = m0 + 8*ty + i;
        float* dst = g_o + ((size_t)bh*2048 + m)*128;
        *(float4*)&dst[4*tx]      = make_float4(o[i][0]*inv, o[i][1]*inv, o[i][2]*inv, o[i][3]*inv);
        *(float4*)&dst[64 + 4*tx] = make_float4(o[i][4]*inv, o[i][5]*inv, o[i][6]*inv, o[i][7]*inv);
    }
}

// ---------------- 5. Out projection: [8192,1024] @ w_out^T + b ------------
__global__ __launch_bounds__(256, 2) void outproj_kernel(const float* __restrict__ w_out,
                                                         const float* __restrict__ b_out,
                                                         float* __restrict__ out) {
    __shared__ float As[32*68];
    __shared__ float Bs[32*132];
    int tid = threadIdx.x;
    int ty = tid >> 4, tx = tid & 15;
    int m0 = blockIdx.x * 64;
    float acc[4][8] = {};
    for (int k0 = 0; k0 < 1024; k0 += 32) {
        __syncthreads();
        for (int idx = tid; idx < 64*32; idx += 256) {
            int r = idx >> 5, kk = idx & 31;
            int m = m0 + r, b = m >> 11, n = m & 2047;
            int kg = k0 + kk, h = kg >> 7, d = kg & 127;
            As[kk*68 + r] = g_o[(((b << 3) + h)*2048 + n)*128 + d];
        }
        for (int idx = tid; idx < 128*32; idx += 256) {
            int c = idx >> 5, kk = idx & 31;
            Bs[kk*132 + c] = w_out[c*1024 + k0 + kk];
        }
        __syncthreads();
#pragma unroll 8
        for (int kk = 0; kk < 32; kk++) {
            float4 a  = *(const float4*)&As[kk*68 + 4*ty];
            float4 b0 = *(const float4*)&Bs[kk*132 + 8*tx];
            float4 b1 = *(const float4*)&Bs[kk*132 + 8*tx + 4];
            float av[4] = {a.x,a.y,a.z,a.w};
            float bv[8] = {b0.x,b0.y,b0.z,b0.w,b1.x,b1.y,b1.z,b1.w};
#pragma unroll
            for (int i = 0; i < 4; i++)
#pragma unroll
                for (int c = 0; c < 8; c++) acc[i][c] += av[i]*bv[c];
        }
    }
#pragma unroll
    for (int i = 0; i < 4; i++) {
        int m = m0 + 4*ty + i;
#pragma unroll
        for (int c = 0; c < 8; c++) {
            int cg = 8*tx + c;
            out[m*128 + cg] = acc[i][c] + b_out[cg];
        }
    }
}

// ---------------- launcher -------------------------------------------------
extern "C" void kernel_launch(void* const* d_in, const int* in_sizes, int n_in,
                              void* d_out, int out_size) {
    const float* x      = (const float*)d_in[0];
    const float* gamma  = (const float*)d_in[1];
    const float* beta   = (const float*)d_in[2];
    const float* w_qkv  = (const float*)d_in[3];
    const float* w_out  = (const float*)d_in[4];
    const float* b_out  = (const float*)d_in[5];
    float* out = (float*)d_out;

    ln_kernel<<<1024, 256>>>(x, gamma, beta);

    cudaFuncSetAttribute(qkv_kernel, cudaFuncAttributeMaxDynamicSharedMemorySize, 102400);
    qkv_kernel<<<dim3(48, 64), 256, 102400>>>(w_qkv);

    rope_kernel<<<dim3(2047, 32), 64>>>();

    cudaFuncSetAttribute(attn_kernel, cudaFuncAttributeMaxDynamicSharedMemorySize, 128000);
    attn_kernel<<<dim3(16, 32), 256, 128000>>>();

    outproj_kernel<<<128, 256>>>(w_out, b_out, out);
}

// round 3
// speedup vs baseline: 2.0695x; 1.4194x over previous
#include <cuda_runtime.h>
#include <math.h>
#include <stdint.h>

#define SEQ   2048
#define NB    4
#define NH    8
#define HD    128
#define ROWS  (NB*SEQ)          // 8192

// ---------------- scratch ----------------
__device__ float g_xn[ROWS*128];
__device__ float g_q[NB*NH*SEQ*HD];
__device__ float g_k[NB*NH*SEQ*HD];
__device__ float g_v[NB*NH*SEQ*HD];
__device__ float g_o[NB*NH*SEQ*HD];

// ---------------- helpers ----------------
__device__ __forceinline__ uint32_t f2tf32(float f) {
    uint32_t u;
    asm("cvt.rna.tf32.f32 %0, %1;" : "=r"(u) : "f"(f));
    return u;
}
__device__ __forceinline__ void mma_tf32(float* c,
        uint32_t a0, uint32_t a1, uint32_t a2, uint32_t a3,
        uint32_t b0, uint32_t b1) {
    asm volatile("mma.sync.aligned.m16n8k8.row.col.f32.tf32.tf32.f32 "
        "{%0,%1,%2,%3}, {%4,%5,%6,%7}, {%8,%9}, {%0,%1,%2,%3};"
        : "+f"(c[0]), "+f"(c[1]), "+f"(c[2]), "+f"(c[3])
        : "r"(a0), "r"(a1), "r"(a2), "r"(a3), "r"(b0), "r"(b1));
}

// ---------------- 1. LayerNorm ---------------------------------------------
__global__ void ln_kernel(const float* __restrict__ x,
                          const float* __restrict__ gamma,
                          const float* __restrict__ beta) {
    int row  = blockIdx.x * 8 + (threadIdx.x >> 5);
    int lane = threadIdx.x & 31;
    float4 v = ((const float4*)(x + (size_t)row * 128))[lane];
    float s  = v.x + v.y + v.z + v.w;
    float s2 = v.x*v.x + v.y*v.y + v.z*v.z + v.w*v.w;
#pragma unroll
    for (int m = 16; m; m >>= 1) {
        s  += __shfl_xor_sync(0xffffffffu, s,  m);
        s2 += __shfl_xor_sync(0xffffffffu, s2, m);
    }
    float mean = s * (1.f/128.f);
    float var  = s2 * (1.f/128.f) - mean*mean;
    float rs   = rsqrtf(var + 1e-5f);
    float4 g = ((const float4*)gamma)[lane];
    float4 b = ((const float4*)beta)[lane];
    float4 o;
    o.x = (v.x-mean)*rs*g.x + b.x;
    o.y = (v.y-mean)*rs*g.y + b.y;
    o.z = (v.z-mean)*rs*g.z + b.z;
    o.w = (v.w-mean)*rs*g.w + b.w;
    ((float4*)(g_xn + (size_t)row*128))[lane] = o;
}

// ---------------- 2. QKV GEMM (fp32 SIMT, as R2) ---------------------------
__global__ __launch_bounds__(256, 1) void qkv_kernel(const float* __restrict__ w) {
    extern __shared__ float sm[];
    float* As = sm;              // [128 kk][132]
    float* Bs = sm + 128*132;    // [128 kk][68]
    int tid = threadIdx.x;
    int n0 = blockIdx.x * 64, m0 = blockIdx.y * 128;
    for (int idx = tid; idx < 128*128; idx += 256) {
        int d = idx & 127, m = idx >> 7;
        As[d*132 + m] = g_xn[(m0 + m)*128 + d];
    }
    for (int idx = tid; idx < 64*128; idx += 256) {
        int d = idx & 127, n = idx >> 7;
        Bs[d*68 + n] = w[(n0 + n)*128 + d];
    }
    __syncthreads();
    int ty = tid >> 4, tx = tid & 15;
    float acc[8][4] = {};
#pragma unroll 8
    for (int kk = 0; kk < 128; kk++) {
        const float* qp = &As[kk*132 + 8*ty];
        float4 a0 = *(const float4*)qp;
        float4 a1 = *(const float4*)(qp + 4);
        float4 b  = *(const float4*)&Bs[kk*68 + 4*tx];
        float av[8] = {a0.x,a0.y,a0.z,a0.w,a1.x,a1.y,a1.z,a1.w};
        float bv[4] = {b.x,b.y,b.z,b.w};
#pragma unroll
        for (int i = 0; i < 8; i++)
#pragma unroll
            for (int j = 0; j < 4; j++) acc[i][j] += av[i]*bv[j];
    }
#pragma unroll
    for (int i = 0; i < 8; i++) {
        int m = m0 + 8*ty + i;
        int b_ = m >> 11, n = m & 2047;
#pragma unroll
        for (int j = 0; j < 4; j++) {
            int e = n0 + 4*tx + j;
            int part = e >> 10, r = e & 1023, h = r >> 7, d = r & 127;
            float* dst = (part == 0) ? g_q : (part == 1 ? g_k : g_v);
            dst[(((b_ << 3) + h)*2048 + n)*128 + d] = acc[i][j];
        }
    }
}

// ---------------- 3. RoPE: all heads, positions 0..2046 --------------------
__global__ void rope_kernel() {
    int n  = blockIdx.x;          // 0..2046
    int bh = blockIdx.y;          // 0..31
    int j  = threadIdx.x;         // 0..63
    float inv = (float)pow(10000.0, -((double)(2*j) / 128.0));
    float ang = (float)n * inv;
    float s, c;
    sincosf(ang, &s, &c);
    int base = (bh*2048 + n)*128 + 2*j;
    float q0 = g_q[base], q1 = g_q[base+1];
    g_q[base]   = q0*c - q1*s;
    g_q[base+1] = q1*c + q0*s;
    float k0 = g_k[base], k1 = g_k[base+1];
    g_k[base]   = k0*c - k1*s;
    g_k[base+1] = k1*c + k0*s;
}

// ---------------- 4. Flash attention, tf32 mma.sync ------------------------
// BM=128, BN=64, 8 warps. Warp w owns rows [16w, 16w+16).
// smem (uint32 tf32): Qs[128][132], Ks[64][132], Vs[64][136], Ps[128][68]
#define QS_LD 132
#define KS_LD 132
#define VS_LD 136
#define PS_LD 68
__global__ __launch_bounds__(256, 1) void attn_kernel() {
    extern __shared__ uint32_t smu[];
    uint32_t* Qs = smu;                    // 128*132
    uint32_t* Ks = Qs + 128*QS_LD;         // 64*132
    uint32_t* Vs = Ks + 64*KS_LD;          // 64*136
    uint32_t* Ps = Vs + 64*VS_LD;          // 128*68
    int tid  = threadIdx.x;
    int wid  = tid >> 5;
    int lane = tid & 31;
    int r    = lane >> 2;       // 0..7
    int cq   = lane & 3;        // 0..3
    int bh   = blockIdx.y;
    int m0   = blockIdx.x * 128;
    int m0w  = wid * 16;
    const float* Q = g_q + (size_t)bh*SEQ*128;
    const float* K = g_k + (size_t)bh*SEQ*128;
    const float* V = g_v + (size_t)bh*SEQ*128;
    const float scale = 0.08838834764831845f;

    // load Q tile (row-major), fold scale, convert tf32
    for (int idx = tid; idx < 128*32; idx += 256) {
        int row = idx >> 5, c4 = (idx & 31) * 4;
        float4 v = *(const float4*)&Q[(m0 + row)*128 + c4];
        uint4 u;
        u.x = f2tf32(v.x*scale); u.y = f2tf32(v.y*scale);
        u.z = f2tf32(v.z*scale); u.w = f2tf32(v.w*scale);
        *(uint4*)&Qs[row*QS_LD + c4] = u;
    }

    float oacc[16][4];
    float mprev0 = -INFINITY, mprev1 = -INFINITY, l0 = 0.f, l1 = 0.f;
#pragma unroll
    for (int nf = 0; nf < 16; nf++)
#pragma unroll
        for (int i = 0; i < 4; i++) oacc[nf][i] = 0.f;

    for (int t = 0; t < 32; t++) {
        int j0 = t * 64;
        __syncthreads();                         // prev tile's Ks/Vs readers done
        for (int idx = tid; idx < 64*32; idx += 256) {
            int row = idx >> 5, c4 = (idx & 31) * 4;
            float4 kv = *(const float4*)&K[(j0 + row)*128 + c4];
            uint4 u;
            u.x = f2tf32(kv.x); u.y = f2tf32(kv.y); u.z = f2tf32(kv.z); u.w = f2tf32(kv.w);
            *(uint4*)&Ks[row*KS_LD + c4] = u;
            float4 vv = *(const float4*)&V[(j0 + row)*128 + c4];
            u.x = f2tf32(vv.x); u.y = f2tf32(vv.y); u.z = f2tf32(vv.z); u.w = f2tf32(vv.w);
            *(uint4*)&Vs[row*VS_LD + c4] = u;
        }
        __syncthreads();

        // ---- S = Q @ K^T : 16 k-steps, 8 n-frags ----
        float sacc[8][4];
#pragma unroll
        for (int nf = 0; nf < 8; nf++)
#pragma unroll
            for (int i = 0; i < 4; i++) sacc[nf][i] = 0.f;
#pragma unroll
        for (int ks = 0; ks < 16; ks++) {
            int k0 = ks * 8;
            uint32_t a0 = Qs[(m0w + r    )*QS_LD + k0 + cq];
            uint32_t a1 = Qs[(m0w + r + 8)*QS_LD + k0 + cq];
            uint32_t a2 = Qs[(m0w + r    )*QS_LD + k0 + cq + 4];
            uint32_t a3 = Qs[(m0w + r + 8)*QS_LD + k0 + cq + 4];
#pragma unroll
            for (int nf = 0; nf < 8; nf++) {
                uint32_t b0 = Ks[(nf*8 + r)*KS_LD + k0 + cq];
                uint32_t b1 = Ks[(nf*8 + r)*KS_LD + k0 + cq + 4];
                mma_tf32(sacc[nf], a0, a1, a2, a3, b0, b1);
            }
        }

        // ---- online softmax (rows r and r+8 of warp tile) ----
        float mx0 = -INFINITY, mx1 = -INFINITY;
#pragma unroll
        for (int nf = 0; nf < 8; nf++) {
            mx0 = fmaxf(mx0, fmaxf(sacc[nf][0], sacc[nf][1]));
            mx1 = fmaxf(mx1, fmaxf(sacc[nf][2], sacc[nf][3]));
        }
        mx0 = fmaxf(mx0, __shfl_xor_sync(0xffffffffu, mx0, 1));
        mx0 = fmaxf(mx0, __shfl_xor_sync(0xffffffffu, mx0, 2));
        mx1 = fmaxf(mx1, __shfl_xor_sync(0xffffffffu, mx1, 1));
        mx1 = fmaxf(mx1, __shfl_xor_sync(0xffffffffu, mx1, 2));
        float mn0 = fmaxf(mprev0, mx0), mn1 = fmaxf(mprev1, mx1);
        float al0 = __expf(mprev0 - mn0), al1 = __expf(mprev1 - mn1);
        float ps0 = 0.f, ps1 = 0.f;
#pragma unroll
        for (int nf = 0; nf < 8; nf++) {
            float p00 = __expf(sacc[nf][0] - mn0);
            float p01 = __expf(sacc[nf][1] - mn0);
            float p10 = __expf(sacc[nf][2] - mn1);
            float p11 = __expf(sacc[nf][3] - mn1);
            ps0 += p00 + p01;  ps1 += p10 + p11;
            Ps[(m0w + r    )*PS_LD + nf*8 + 2*cq    ] = f2tf32(p00);
            Ps[(m0w + r    )*PS_LD + nf*8 + 2*cq + 1] = f2tf32(p01);
            Ps[(m0w + r + 8)*PS_LD + nf*8 + 2*cq    ] = f2tf32(p10);
            Ps[(m0w + r + 8)*PS_LD + nf*8 + 2*cq + 1] = f2tf32(p11);
        }
        ps0 += __shfl_xor_sync(0xffffffffu, ps0, 1);
        ps0 += __shfl_xor_sync(0xffffffffu, ps0, 2);
        ps1 += __shfl_xor_sync(0xffffffffu, ps1, 1);
        ps1 += __shfl_xor_sync(0xffffffffu, ps1, 2);
        l0 = l0*al0 + ps0;  l1 = l1*al1 + ps1;
        mprev0 = mn0;       mprev1 = mn1;
#pragma unroll
        for (int nf = 0; nf < 16; nf++) {
            oacc[nf][0] *= al0; oacc[nf][1] *= al0;
            oacc[nf][2] *= al1; oacc[nf][3] *= al1;
        }
        __syncwarp();    // publish own-row Ps writes to own warp

        // ---- O += P @ V : 8 k-steps (j), 16 n-frags (d) ----
#pragma unroll
        for (int ks = 0; ks < 8; ks++) {
            int k0 = ks * 8;
            uint32_t a0 = Ps[(m0w + r    )*PS_LD + k0 + cq];
            uint32_t a1 = Ps[(m0w + r + 8)*PS_LD + k0 + cq];
            uint32_t a2 = Ps[(m0w + r    )*PS_LD + k0 + cq + 4];
            uint32_t a3 = Ps[(m0w + r + 8)*PS_LD + k0 + cq + 4];
#pragma unroll
            for (int nf = 0; nf < 16; nf++) {
                uint32_t b0 = Vs[(k0 + cq    )*VS_LD + nf*8 + r];
                uint32_t b1 = Vs[(k0 + cq + 4)*VS_LD + nf*8 + r];
                mma_tf32(oacc[nf], a0, a1, a2, a3, b0, b1);
            }
        }
    }
    // ---- epilogue ----
    float inv0 = 1.f / l0, inv1 = 1.f / l1;
    float* dst0 = g_o + ((size_t)bh*2048 + m0 + m0w + r    )*128;
    float* dst1 = g_o + ((size_t)bh*2048 + m0 + m0w + r + 8)*128;
#pragma unroll
    for (int nf = 0; nf < 16; nf++) {
        int col = nf*8 + 2*cq;
        *(float2*)&dst0[col] = make_float2(oacc[nf][0]*inv0, oacc[nf][1]*inv0);
        *(float2*)&dst1[col] = make_float2(oacc[nf][2]*inv1, oacc[nf][3]*inv1);
    }
}

// ---------------- 5. Out projection (fp32, as R2) --------------------------
__global__ __launch_bounds__(256, 2) void outproj_kernel(const float* __restrict__ w_out,
                                                         const float* __restrict__ b_out,
                                                         float* __restrict__ out) {
    __shared__ float As[32*68];
    __shared__ float Bs[32*132];
    int tid = threadIdx.x;
    int ty = tid >> 4, tx = tid & 15;
    int m0 = blockIdx.x * 64;
    float acc[4][8] = {};
    for (int k0 = 0; k0 < 1024; k0 += 32) {
        __syncthreads();
        for (int idx = tid; idx < 64*32; idx += 256) {
            int rr = idx >> 5, kk = idx & 31;
            int m = m0 + rr, b = m >> 11, n = m & 2047;
            int kg = k0 + kk, h = kg >> 7, d = kg & 127;
            As[kk*68 + rr] = g_o[(((b << 3) + h)*2048 + n)*128 + d];
        }
        for (int idx = tid; idx < 128*32; idx += 256) {
            int c = idx >> 5, kk = idx & 31;
            Bs[kk*132 + c] = w_out[c*1024 + k0 + kk];
        }
        __syncthreads();
#pragma unroll 8
        for (int kk = 0; kk < 32; kk++) {
            float4 a  = *(const float4*)&As[kk*68 + 4*ty];
            float4 b0 = *(const float4*)&Bs[kk*132 + 8*tx];
            float4 b1 = *(const float4*)&Bs[kk*132 + 8*tx + 4];
            float av[4] = {a.x,a.y,a.z,a.w};
            float bv[8] = {b0.x,b0.y,b0.z,b0.w,b1.x,b1.y,b1.z,b1.w};
#pragma unroll
            for (int i = 0; i < 4; i++)
#pragma unroll
                for (int c = 0; c < 8; c++) acc[i][c] += av[i]*bv[c];
        }
    }
#pragma unroll
    for (int i = 0; i < 4; i++) {
        int m = m0 + 4*ty + i;
#pragma unroll
        for (int c = 0; c < 8; c++) {
            int cg = 8*tx + c;
            out[m*128 + cg] = acc[i][c] + b_out[cg];
        }
    }
}

// ---------------- launcher -------------------------------------------------
extern "C" void kernel_launch(void* const* d_in, const int* in_sizes, int n_in,
                              void* d_out, int out_size) {
    const float* x      = (const float*)d_in[0];
    const float* gamma  = (const float*)d_in[1];
    const float* beta   = (const float*)d_in[2];
    const float* w_qkv  = (const float*)d_in[3];
    const float* w_out  = (const float*)d_in[4];
    const float* b_out  = (const float*)d_in[5];
    float* out = (float*)d_out;

    ln_kernel<<<1024, 256>>>(x, gamma, beta);

    cudaFuncSetAttribute(qkv_kernel, cudaFuncAttributeMaxDynamicSharedMemorySize, 102400);
    qkv_kernel<<<dim3(48, 64), 256, 102400>>>(w_qkv);

    rope_kernel<<<dim3(2047, 32), 64>>>();

    // smem: (128*132 + 64*132 + 64*136 + 128*68) * 4 = 171008 bytes
    cudaFuncSetAttribute(attn_kernel, cudaFuncAttributeMaxDynamicSharedMemorySize, 171008);
    attn_kernel<<<dim3(16, 32), 256, 171008>>>();

    outproj_kernel<<<128, 256>>>(w_out, b_out, out);
}

// round 4
// speedup vs baseline: 3.0394x; 1.4686x over previous
#include <cuda_runtime.h>
#include <math.h>
#include <stdint.h>

#define SEQ   2048
#define NB    4
#define NH    8
#define HD    128
#define ROWS  (NB*SEQ)          // 8192

// ---------------- scratch ----------------
__device__ float g_xn[ROWS*128];
__device__ float g_q[NB*NH*SEQ*HD];   // holds tf32-bit floats, q pre-scaled
__device__ float g_k[NB*NH*SEQ*HD];   // tf32-bit floats
__device__ float g_v[NB*NH*SEQ*HD];   // tf32-bit floats
__device__ float g_o[NB*NH*SEQ*HD];
__device__ float g_invf[64];

// ---------------- helpers ----------------
__device__ __forceinline__ uint32_t f2tf32(float f) {
    uint32_t u;
    asm("cvt.rna.tf32.f32 %0, %1;" : "=r"(u) : "f"(f));
    return u;
}
__device__ __forceinline__ void mma_tf32(float* c,
        uint32_t a0, uint32_t a1, uint32_t a2, uint32_t a3,
        uint32_t b0, uint32_t b1) {
    asm volatile("mma.sync.aligned.m16n8k8.row.col.f32.tf32.tf32.f32 "
        "{%0,%1,%2,%3}, {%4,%5,%6,%7}, {%8,%9}, {%0,%1,%2,%3};"
        : "+f"(c[0]), "+f"(c[1]), "+f"(c[2]), "+f"(c[3])
        : "r"(a0), "r"(a1), "r"(a2), "r"(a3), "r"(b0), "r"(b1));
}

// ---------------- 0. inv_freq table (double pow, once) ---------------------
__global__ void init_invf() {
    int j = threadIdx.x;
    g_invf[j] = (float)pow(10000.0, -((double)(2*j) / 128.0));
}

// ---------------- 1. LayerNorm ---------------------------------------------
__global__ void ln_kernel(const float* __restrict__ x,
                          const float* __restrict__ gamma,
                          const float* __restrict__ beta) {
    int row  = blockIdx.x * 8 + (threadIdx.x >> 5);
    int lane = threadIdx.x & 31;
    float4 v = ((const float4*)(x + (size_t)row * 128))[lane];
    float s  = v.x + v.y + v.z + v.w;
    float s2 = v.x*v.x + v.y*v.y + v.z*v.z + v.w*v.w;
#pragma unroll
    for (int m = 16; m; m >>= 1) {
        s  += __shfl_xor_sync(0xffffffffu, s,  m);
        s2 += __shfl_xor_sync(0xffffffffu, s2, m);
    }
    float mean = s * (1.f/128.f);
    float var  = s2 * (1.f/128.f) - mean*mean;
    float rs   = rsqrtf(var + 1e-5f);
    float4 g = ((const float4*)gamma)[lane];
    float4 b = ((const float4*)beta)[lane];
    float4 o;
    o.x = (v.x-mean)*rs*g.x + b.x;
    o.y = (v.y-mean)*rs*g.y + b.y;
    o.z = (v.z-mean)*rs*g.z + b.z;
    o.w = (v.w-mean)*rs*g.w + b.w;
    ((float4*)(g_xn + (size_t)row*128))[lane] = o;
}

// ---------------- 2. QKV GEMM, tf32 mma, fused RoPE+scale ------------------
// BM=128 (8 warps x 16 rows), BN=64, K=128. Fragment-permuted smem.
// Aperm [8w][16ks][32lane][4] ; Bperm [4pair][16ks][32][4]
__global__ __launch_bounds__(256, 2) void qkv_kernel(const float* __restrict__ w) {
    extern __shared__ uint32_t smu[];
    uint32_t* Ap = smu;            // 16384
    uint32_t* Bp = smu + 16384;    // 8192
    int tid = threadIdx.x, wid = tid >> 5, lane = tid & 31;
    int r = lane >> 2, cq = lane & 3;
    int n0 = blockIdx.x * 64, m0 = blockIdx.y * 128;

    // A loader: g_xn rows m0..m0+127, cvt tf32, permute
    for (int idx = tid; idx < 128*32; idx += 256) {
        int row = idx >> 5, c4 = (idx & 31) * 4;
        float4 v = *(const float4*)&g_xn[(m0 + row)*128 + c4];
        int wq = row >> 4, rl = row & 15, rr = rl & 7, a01 = rl >> 3;
        int ks = c4 >> 3, half = (c4 & 7) >> 2;
        int base = ((wq*16 + ks)*32 + (rr << 2))*4 + (half << 1) + a01;
        Ap[base     ] = f2tf32(v.x);
        Ap[base + 4 ] = f2tf32(v.y);
        Ap[base + 8 ] = f2tf32(v.z);
        Ap[base + 12] = f2tf32(v.w);
    }
    // B loader: w rows n0..n0+63
    for (int idx = tid; idx < 64*32; idx += 256) {
        int n = idx >> 5, c4 = (idx & 31) * 4;
        float4 v = *(const float4*)&w[(n0 + n)*128 + c4];
        int nf = n >> 3, rr = n & 7, pair = nf >> 1, hi = nf & 1;
        int ks = c4 >> 3, half = (c4 & 7) >> 2;
        int base = ((pair*16 + ks)*32 + (rr << 2))*4 + (hi << 1) + half;
        Bp[base     ] = f2tf32(v.x);
        Bp[base + 4 ] = f2tf32(v.y);
        Bp[base + 8 ] = f2tf32(v.z);
        Bp[base + 12] = f2tf32(v.w);
    }
    __syncthreads();

    float acc[8][4];
#pragma unroll
    for (int nf = 0; nf < 8; nf++)
#pragma unroll
        for (int i = 0; i < 4; i++) acc[nf][i] = 0.f;
#pragma unroll
    for (int ks = 0; ks < 16; ks++) {
        uint4 A = *(const uint4*)&Ap[((wid*16 + ks)*32 + lane)*4];
#pragma unroll
        for (int p = 0; p < 4; p++) {
            uint4 B = *(const uint4*)&Bp[((p*16 + ks)*32 + lane)*4];
            mma_tf32(acc[2*p    ], A.x, A.y, A.z, A.w, B.x, B.y);
            mma_tf32(acc[2*p + 1], A.x, A.y, A.z, A.w, B.z, B.w);
        }
    }

    // ---- epilogue: rope (+scale for q), cvt tf32, scatter ----
    int part = n0 >> 10;                      // 0=q 1=k 2=v, constant per block
    uint32_t* dst = (uint32_t*)((part == 0) ? g_q : (part == 1 ? g_k : g_v));
    const float scale = 0.08838834764831845f;
    int m_lo = m0 + wid*16 + r;
    int m_hi = m_lo + 8;
    int b_lo = m_lo >> 11, n_lo = m_lo & 2047;
    int b_hi = m_hi >> 11, n_hi = m_hi & 2047;
#pragma unroll
    for (int nf = 0; nf < 8; nf++) {
        int e  = n0 + nf*8 + 2*cq;            // even global col
        int h  = (e & 1023) >> 7;
        int d  = e & 127;
        float v0 = acc[nf][0], v1 = acc[nf][1];    // row m_lo, cols d, d+1
        float v2 = acc[nf][2], v3 = acc[nf][3];    // row m_hi
        if (part < 2) {
            float invf = g_invf[d >> 1];
            if (n_lo < 2047) {
                float sn, cs; sincosf((float)n_lo * invf, &sn, &cs);
                float t0 = v0*cs - v1*sn, t1 = v1*cs + v0*sn;
                v0 = t0; v1 = t1;
            }
            if (n_hi < 2047) {
                float sn, cs; sincosf((float)n_hi * invf, &sn, &cs);
                float t2 = v2*cs - v3*sn, t3 = v3*cs + v2*sn;
                v2 = t2; v3 = t3;
            }
            if (part == 0) { v0 *= scale; v1 *= scale; v2 *= scale; v3 *= scale; }
        }
        uint32_t* p_lo = &dst[((size_t)((b_lo << 3) + h)*2048 + n_lo)*128 + d];
        uint32_t* p_hi = &dst[((size_t)((b_hi << 3) + h)*2048 + n_hi)*128 + d];
        p_lo[0] = f2tf32(v0); p_lo[1] = f2tf32(v1);
        p_hi[0] = f2tf32(v2); p_hi[1] = f2tf32(v3);
    }
}

// ---------------- 3. Flash attention, tf32 mma, permuted frags -------------
// BM=64 (4 warps x 16 rows), BN=64, 128 threads, 2 CTAs/SM.
// Qp[4][16][32][4]  Kp[4][16][32][4]  Vp[8][8][32][4]  Ps[64][68]
__global__ __launch_bounds__(128, 2) void attn_kernel() {
    extern __shared__ uint32_t smu[];
    uint32_t* Qp = smu;             // 8192
    uint32_t* Kp = smu + 8192;      // 8192
    uint32_t* Vp = Kp + 8192;       // 8192
    uint32_t* Ps = Vp + 8192;       // 64*68 = 4352
    int tid  = threadIdx.x;
    int wid  = tid >> 5, lane = tid & 31;
    int r    = lane >> 2, cq = lane & 3;
    int bh   = blockIdx.y;
    int m0   = blockIdx.x * 64;
    int m0w  = wid * 16;
    const uint32_t* Q = (const uint32_t*)g_q + (size_t)bh*SEQ*128;
    const uint32_t* K = (const uint32_t*)g_k + (size_t)bh*SEQ*128;
    const uint32_t* V = (const uint32_t*)g_v + (size_t)bh*SEQ*128;

    // ---- Q tile: permute-copy (already tf32, scale folded) ----
    for (int idx = tid; idx < 64*32; idx += 128) {
        int row = idx >> 5, c4 = (idx & 31) * 4;
        uint4 u = *(const uint4*)&Q[(m0 + row)*128 + c4];
        int wq = row >> 4, rl = row & 15, rr = rl & 7, a01 = rl >> 3;
        int ks = c4 >> 3, half = (c4 & 7) >> 2;
        int base = ((wq*16 + ks)*32 + (rr << 2))*4 + (half << 1) + a01;
        Qp[base] = u.x; Qp[base+4] = u.y; Qp[base+8] = u.z; Qp[base+12] = u.w;
    }

    float oacc[16][4];
    float mprev0 = -INFINITY, mprev1 = -INFINITY, l0 = 0.f, l1 = 0.f;
#pragma unroll
    for (int nf = 0; nf < 16; nf++)
#pragma unroll
        for (int i = 0; i < 4; i++) oacc[nf][i] = 0.f;

    for (int t = 0; t < 32; t++) {
        int j0 = t * 64;
        __syncthreads();
        // K permute-load
        for (int idx = tid; idx < 64*32; idx += 128) {
            int n = idx >> 5, c4 = (idx & 31) * 4;
            uint4 u = *(const uint4*)&K[(j0 + n)*128 + c4];
            int nf = n >> 3, rr = n & 7, pair = nf >> 1, hi = nf & 1;
            int ks = c4 >> 3, half = (c4 & 7) >> 2;
            int base = ((pair*16 + ks)*32 + (rr << 2))*4 + (hi << 1) + half;
            Kp[base] = u.x; Kp[base+4] = u.y; Kp[base+8] = u.z; Kp[base+12] = u.w;
        }
        // V permute-load
        for (int idx = tid; idx < 64*32; idx += 128) {
            int j = idx >> 5, c4 = (idx & 31) * 4;
            uint4 u = *(const uint4*)&V[(j0 + j)*128 + c4];
            int ks = j >> 3, cj = j & 7, half = cj >> 2, cqv = cj & 3;
            int nf = c4 >> 3, pair = nf >> 1, hi = nf & 1, rbase = c4 & 7;
            int reg = (hi << 1) + half;
            int base = ((pair*8 + ks)*32 + (rbase << 2) + cqv)*4 + reg;
            Vp[base] = u.x; Vp[base+16] = u.y; Vp[base+32] = u.z; Vp[base+48] = u.w;
        }
        __syncthreads();

        // ---- S = Q @ K^T ----
        float sacc[8][4];
#pragma unroll
        for (int nf = 0; nf < 8; nf++)
#pragma unroll
            for (int i = 0; i < 4; i++) sacc[nf][i] = 0.f;
#pragma unroll
        for (int ks = 0; ks < 16; ks++) {
            uint4 A = *(const uint4*)&Qp[((wid*16 + ks)*32 + lane)*4];
#pragma unroll
            for (int p = 0; p < 4; p++) {
                uint4 B = *(const uint4*)&Kp[((p*16 + ks)*32 + lane)*4];
                mma_tf32(sacc[2*p    ], A.x, A.y, A.z, A.w, B.x, B.y);
                mma_tf32(sacc[2*p + 1], A.x, A.y, A.z, A.w, B.z, B.w);
            }
        }

        // ---- online softmax ----
        float mx0 = -INFINITY, mx1 = -INFINITY;
#pragma unroll
        for (int nf = 0; nf < 8; nf++) {
            mx0 = fmaxf(mx0, fmaxf(sacc[nf][0], sacc[nf][1]));
            mx1 = fmaxf(mx1, fmaxf(sacc[nf][2], sacc[nf][3]));
        }
        mx0 = fmaxf(mx0, __shfl_xor_sync(0xffffffffu, mx0, 1));
        mx0 = fmaxf(mx0, __shfl_xor_sync(0xffffffffu, mx0, 2));
        mx1 = fmaxf(mx1, __shfl_xor_sync(0xffffffffu, mx1, 1));
        mx1 = fmaxf(mx1, __shfl_xor_sync(0xffffffffu, mx1, 2));
        float mn0 = fmaxf(mprev0, mx0), mn1 = fmaxf(mprev1, mx1);
        float al0 = __expf(mprev0 - mn0), al1 = __expf(mprev1 - mn1);
        float ps0 = 0.f, ps1 = 0.f;
#pragma unroll
        for (int nf = 0; nf < 8; nf++) {
            float p00 = __expf(sacc[nf][0] - mn0);
            float p01 = __expf(sacc[nf][1] - mn0);
            float p10 = __expf(sacc[nf][2] - mn1);
            float p11 = __expf(sacc[nf][3] - mn1);
            ps0 += p00 + p01;  ps1 += p10 + p11;
            Ps[(m0w + r    )*68 + nf*8 + 2*cq    ] = f2tf32(p00);
            Ps[(m0w + r    )*68 + nf*8 + 2*cq + 1] = f2tf32(p01);
            Ps[(m0w + r + 8)*68 + nf*8 + 2*cq    ] = f2tf32(p10);
            Ps[(m0w + r + 8)*68 + nf*8 + 2*cq + 1] = f2tf32(p11);
        }
        ps0 += __shfl_xor_sync(0xffffffffu, ps0, 1);
        ps0 += __shfl_xor_sync(0xffffffffu, ps0, 2);
        ps1 += __shfl_xor_sync(0xffffffffu, ps1, 1);
        ps1 += __shfl_xor_sync(0xffffffffu, ps1, 2);
        l0 = l0*al0 + ps0;  l1 = l1*al1 + ps1;
        mprev0 = mn0;       mprev1 = mn1;
#pragma unroll
        for (int nf = 0; nf < 16; nf++) {
            oacc[nf][0] *= al0; oacc[nf][1] *= al0;
            oacc[nf][2] *= al1; oacc[nf][3] *= al1;
        }
        __syncwarp();   // own-warp Ps rows published

        // ---- O += P @ V ----
#pragma unroll
        for (int ks = 0; ks < 8; ks++) {
            int k0 = ks * 8;
            uint32_t a0 = Ps[(m0w + r    )*68 + k0 + cq];
            uint32_t a1 = Ps[(m0w + r + 8)*68 + k0 + cq];
            uint32_t a2 = Ps[(m0w + r    )*68 + k0 + cq + 4];
            uint32_t a3 = Ps[(m0w + r + 8)*68 + k0 + cq + 4];
#pragma unroll
            for (int p = 0; p < 8; p++) {
                uint4 B = *(const uint4*)&Vp[((p*8 + ks)*32 + lane)*4];
                mma_tf32(oacc[2*p    ], a0, a1, a2, a3, B.x, B.y);
                mma_tf32(oacc[2*p + 1], a0, a1, a2, a3, B.z, B.w);
            }
        }
    }
    // ---- epilogue ----
    float inv0 = 1.f / l0, inv1 = 1.f / l1;
    float* dst0 = g_o + ((size_t)bh*2048 + m0 + m0w + r    )*128;
    float* dst1 = g_o + ((size_t)bh*2048 + m0 + m0w + r + 8)*128;
#pragma unroll
    for (int nf = 0; nf < 16; nf++) {
        int col = nf*8 + 2*cq;
        *(float2*)&dst0[col] = make_float2(oacc[nf][0]*inv0, oacc[nf][1]*inv0);
        *(float2*)&dst1[col] = make_float2(oacc[nf][2]*inv1, oacc[nf][3]*inv1);
    }
}

// ---------------- 4. Out projection, tf32 mma ------------------------------
// BM=64 (4 warps), N=128, K=1024 in 16 chunks of 64. 128 threads.
__global__ __launch_bounds__(128, 2) void outproj_kernel(const float* __restrict__ w_out,
                                                         const float* __restrict__ b_out,
                                                         float* __restrict__ out) {
    __shared__ uint32_t Ap[4*8*32*4];   // 4096
    __shared__ uint32_t Bp[8*8*32*4];   // 8192
    int tid = threadIdx.x, wid = tid >> 5, lane = tid & 31;
    int r = lane >> 2, cq = lane & 3;
    int m0 = blockIdx.x * 64;

    float acc[16][4];
#pragma unroll
    for (int nf = 0; nf < 16; nf++)
#pragma unroll
        for (int i = 0; i < 4; i++) acc[nf][i] = 0.f;

    for (int kc = 0; kc < 16; kc++) {
        int k0c = kc * 64;
        __syncthreads();
        // A: 64 rows x 64 k from g_o (head-interleaved), cvt tf32
        for (int idx = tid; idx < 64*16; idx += 128) {
            int row = idx >> 4, c4 = (idx & 15) * 4;
            int kg = k0c + c4;
            int m = m0 + row, b = m >> 11, n = m & 2047;
            int h = kg >> 7, d = kg & 127;
            float4 v = *(const float4*)&g_o[((size_t)((b << 3) + h)*2048 + n)*128 + d];
            int wq = row >> 4, rl = row & 15, rr = rl & 7, a01 = rl >> 3;
            int ks = c4 >> 3, half = (c4 & 7) >> 2;
            int base = ((wq*8 + ks)*32 + (rr << 2))*4 + (half << 1) + a01;
            Ap[base] = f2tf32(v.x); Ap[base+4] = f2tf32(v.y);
            Ap[base+8] = f2tf32(v.z); Ap[base+12] = f2tf32(v.w);
        }
        // B: 128 n x 64 k from w_out
        for (int idx = tid; idx < 128*16; idx += 128) {
            int n = idx >> 4, c4 = (idx & 15) * 4;
            float4 v = *(const float4*)&w_out[(size_t)n*1024 + k0c + c4];
            int nf = n >> 3, rr = n & 7, pair = nf >> 1, hi = nf & 1;
            int ks = c4 >> 3, half = (c4 & 7) >> 2;
            int base = ((pair*8 + ks)*32 + (rr << 2))*4 + (hi << 1) + half;
            Bp[base] = f2tf32(v.x); Bp[base+4] = f2tf32(v.y);
            Bp[base+8] = f2tf32(v.z); Bp[base+12] = f2tf32(v.w);
        }
        __syncthreads();
#pragma unroll
        for (int ks = 0; ks < 8; ks++) {
            uint4 A = *(const uint4*)&Ap[((wid*8 + ks)*32 + lane)*4];
#pragma unroll
            for (int p = 0; p < 8; p++) {
                uint4 B = *(const uint4*)&Bp[((p*8 + ks)*32 + lane)*4];
                mma_tf32(acc[2*p    ], A.x, A.y, A.z, A.w, B.x, B.y);
                mma_tf32(acc[2*p + 1], A.x, A.y, A.z, A.w, B.z, B.w);
            }
        }
    }
#pragma unroll
    for (int nf = 0; nf < 16; nf++) {
        int col = nf*8 + 2*cq;
        float b0 = b_out[col], b1 = b_out[col + 1];
        int mlo = m0 + wid*16 + r;
        *(float2*)&out[(size_t)mlo*128 + col] =
            make_float2(acc[nf][0] + b0, acc[nf][1] + b1);
        *(float2*)&out[(size_t)(mlo + 8)*128 + col] =
            make_float2(acc[nf][2] + b0, acc[nf][3] + b1);
    }
}

// ---------------- launcher -------------------------------------------------
extern "C" void kernel_launch(void* const* d_in, const int* in_sizes, int n_in,
                              void* d_out, int out_size) {
    const float* x      = (const float*)d_in[0];
    const float* gamma  = (const float*)d_in[1];
    const float* beta   = (const float*)d_in[2];
    const float* w_qkv  = (const float*)d_in[3];
    const float* w_out  = (const float*)d_in[4];
    const float* b_out  = (const float*)d_in[5];
    float* out = (float*)d_out;

    init_invf<<<1, 64>>>();
    ln_kernel<<<1024, 256>>>(x, gamma, beta);

    cudaFuncSetAttribute(qkv_kernel, cudaFuncAttributeMaxDynamicSharedMemorySize, 98304);
    qkv_kernel<<<dim3(48, 64), 256, 98304>>>(w_qkv);

    cudaFuncSetAttribute(attn_kernel, cudaFuncAttributeMaxDynamicSharedMemorySize, 115712);
    attn_kernel<<<dim3(32, 32), 128, 115712>>>();

    outproj_kernel<<<128, 128>>>(w_out, b_out, out);
}

// round 5
// speedup vs baseline: 5.4228x; 1.7842x over previous
#include <cuda_runtime.h>
#include <math.h>
#include <stdint.h>

#define SEQ   2048
#define NB    4
#define NH    8
#define HD    128
#define ROWS  (NB*SEQ)          // 8192

// ---------------- scratch (all fragment-permuted, tf32 bits) ---------------
// g_xn : per 128-row block: [wq8][ks16][lane32][reg4]            (16384 w/blk)
// g_q  : per (bh, 128-row qblock): [wq8][ks16][lane32][reg4]     (16384 w/blk)
// g_k  : per (bh, 64-row kblock):  [pair4][ks16][lane32][reg4]   ( 8192 w/blk)
// g_v  : per (bh, 64-row kblock):  [pair8][ks8][lane32][reg4]    ( 8192 w/blk)
// g_o  : per (64-row mblock, 64-col kchunk): [wq4][ks8][lane32][reg4] (4096 w)
__device__ float g_xn[ROWS*128];
__device__ float g_q[NB*NH*SEQ*HD];
__device__ float g_k[NB*NH*SEQ*HD];
__device__ float g_v[NB*NH*SEQ*HD];
__device__ float g_o[NB*NH*SEQ*HD];
__device__ float g_invf[64];

// ---------------- helpers ----------------
__device__ __forceinline__ uint32_t f2tf32(float f) {
    uint32_t u;
    asm("cvt.rna.tf32.f32 %0, %1;" : "=r"(u) : "f"(f));
    return u;
}
__device__ __forceinline__ void mma_tf32(float* c,
        uint32_t a0, uint32_t a1, uint32_t a2, uint32_t a3,
        uint32_t b0, uint32_t b1) {
    asm volatile("mma.sync.aligned.m16n8k8.row.col.f32.tf32.tf32.f32 "
        "{%0,%1,%2,%3}, {%4,%5,%6,%7}, {%8,%9}, {%0,%1,%2,%3};"
        : "+f"(c[0]), "+f"(c[1]), "+f"(c[2]), "+f"(c[3])
        : "r"(a0), "r"(a1), "r"(a2), "r"(a3), "r"(b0), "r"(b1));
}

// ---------------- 0. inv_freq table ----------------------------------------
__global__ void init_invf() {
    int j = threadIdx.x;
    g_invf[j] = (float)pow(10000.0, -((double)(2*j) / 128.0));
}

// ---------------- 1. LayerNorm -> permuted tf32 g_xn ------------------------
__global__ void ln_kernel(const float* __restrict__ x,
                          const float* __restrict__ gamma,
                          const float* __restrict__ beta) {
    int row  = blockIdx.x * 8 + (threadIdx.x >> 5);
    int lane = threadIdx.x & 31;
    float4 v = ((const float4*)(x + (size_t)row * 128))[lane];
    float s  = v.x + v.y + v.z + v.w;
    float s2 = v.x*v.x + v.y*v.y + v.z*v.z + v.w*v.w;
#pragma unroll
    for (int m = 16; m; m >>= 1) {
        s  += __shfl_xor_sync(0xffffffffu, s,  m);
        s2 += __shfl_xor_sync(0xffffffffu, s2, m);
    }
    float mean = s * (1.f/128.f);
    float var  = s2 * (1.f/128.f) - mean*mean;
    float rs   = rsqrtf(var + 1e-5f);
    float4 g = ((const float4*)gamma)[lane];
    float4 b = ((const float4*)beta)[lane];
    float o0 = (v.x-mean)*rs*g.x + b.x;
    float o1 = (v.y-mean)*rs*g.y + b.y;
    float o2 = (v.z-mean)*rs*g.z + b.z;
    float o3 = (v.w-mean)*rs*g.w + b.w;
    // permuted store: cols 4*lane .. 4*lane+3
    uint32_t* dst = (uint32_t*)g_xn + (size_t)(row >> 7)*16384;
    int rl  = row & 127;
    int wq  = rl >> 4, rr = rl & 7, a01 = (rl >> 3) & 1;
    int wbase = ((wq*16 + (lane >> 1))*32 + rr*4)*4 + ((lane & 1) << 1) + a01;
    dst[wbase     ] = f2tf32(o0);
    dst[wbase + 4 ] = f2tf32(o1);
    dst[wbase + 8 ] = f2tf32(o2);
    dst[wbase + 12] = f2tf32(o3);
}

// ---------------- 2. QKV GEMM, tf32 mma, fused RoPE+scale ------------------
// BM=128 (8 warps x 16 rows), BN=64. A: pure copy from permuted g_xn.
__global__ __launch_bounds__(256) void qkv_kernel(const float* __restrict__ w) {
    extern __shared__ uint32_t smu[];
    uint32_t* Ap = smu;            // 16384 w
    uint32_t* Bp = smu + 16384;    // 8192 w
    int tid = threadIdx.x, wid = tid >> 5, lane = tid & 31;
    int r = lane >> 2, cq = lane & 3;
    int n0 = blockIdx.x * 64, m0 = blockIdx.y * 128;

    // A: coalesced uint4 copy
    {
        const uint4* Ag = (const uint4*)((const uint32_t*)g_xn + (size_t)blockIdx.y*16384);
        uint4* Ap4 = (uint4*)Ap;
        for (int i = tid; i < 4096; i += 256) Ap4[i] = Ag[i];
    }
    // B: gather-LDG -> STS.128 (conflict-free)
    for (int g = tid; g < 2048; g += 256) {
        int pair = g >> 9, ks = (g >> 5) & 15, lt = g & 31;
        int rr = lt >> 2, ca = lt & 3;
        int rowb = n0 + pair*16 + rr;
        int col  = ks*8 + ca;
        uint4 u;
        u.x = f2tf32(w[(size_t)rowb*128 + col]);
        u.y = f2tf32(w[(size_t)rowb*128 + col + 4]);
        u.z = f2tf32(w[(size_t)(rowb+8)*128 + col]);
        u.w = f2tf32(w[(size_t)(rowb+8)*128 + col + 4]);
        ((uint4*)Bp)[g] = u;
    }
    __syncthreads();

    float acc[8][4];
#pragma unroll
    for (int nf = 0; nf < 8; nf++)
#pragma unroll
        for (int i = 0; i < 4; i++) acc[nf][i] = 0.f;
#pragma unroll
    for (int ks = 0; ks < 16; ks++) {
        uint4 A = ((const uint4*)Ap)[(wid*16 + ks)*32 + lane];
#pragma unroll
        for (int p = 0; p < 4; p++) {
            uint4 B = ((const uint4*)Bp)[(p*16 + ks)*32 + lane];
            mma_tf32(acc[2*p    ], A.x, A.y, A.z, A.w, B.x, B.y);
            mma_tf32(acc[2*p + 1], A.x, A.y, A.z, A.w, B.z, B.w);
        }
    }

    // ---- epilogue: rope (+scale for q), scatter to permuted global ----
    int part = n0 >> 10;                      // 0=q 1=k 2=v
    const float scale = 0.08838834764831845f;
    int m_lo = m0 + wid*16 + r;
    int b_   = m_lo >> 11;
    int n_lo = m_lo & 2047;
    int n_hi = n_lo + 8;
#pragma unroll
    for (int nf = 0; nf < 8; nf++) {
        int e = n0 + nf*8 + 2*cq;
        int h = (e & 1023) >> 7;
        int d = e & 127;
        float v0 = acc[nf][0], v1 = acc[nf][1];
        float v2 = acc[nf][2], v3 = acc[nf][3];
        if (part < 2) {
            float invf = g_invf[d >> 1];
            if (n_lo < 2047) {
                float sn, cs; sincosf((float)n_lo * invf, &sn, &cs);
                float t0 = v0*cs - v1*sn; v1 = v1*cs + v0*sn; v0 = t0;
            }
            if (n_hi < 2047) {
                float sn, cs; sincosf((float)n_hi * invf, &sn, &cs);
                float t2 = v2*cs - v3*sn; v3 = v3*cs + v2*sn; v2 = t2;
            }
            if (part == 0) { v0*=scale; v1*=scale; v2*=scale; v3*=scale; }
        }
        int bh_ = b_*8 + h;
        if (part == 0) {
            uint32_t* base = (uint32_t*)g_q + ((size_t)bh_*16 + (n_lo >> 7))*16384;
            int w0 = ((wid*16 + (d >> 3))*32 + r*4 + (d & 3))*4 + (((d & 7) >> 2) << 1);
            base[w0    ] = f2tf32(v0); base[w0 + 4] = f2tf32(v1);
            base[w0 + 1] = f2tf32(v2); base[w0 + 5] = f2tf32(v3);
        } else if (part == 1) {
            uint32_t* base = (uint32_t*)g_k + ((size_t)bh_*32 + (n_lo >> 6))*8192;
            int pair = wid & 3;
            int w0 = ((pair*16 + (d >> 3))*32 + r*4 + (d & 3))*4 + ((d & 7) >> 2);
            base[w0    ] = f2tf32(v0); base[w0 + 4] = f2tf32(v1);
            base[w0 + 2] = f2tf32(v2); base[w0 + 6] = f2tf32(v3);
        } else {
            uint32_t* base = (uint32_t*)g_v + ((size_t)bh_*32 + (n_lo >> 6))*8192;
            int ks_lo = (wid & 3)*2, half_k = r >> 2, cqv = r & 3;
            int w0 = (((d >> 4)*8 + ks_lo)*32 + (d & 7)*4 + cqv)*4
                     + (((d >> 3) & 1) << 1) + half_k;
            base[w0      ] = f2tf32(v0); base[w0 + 16 ] = f2tf32(v1);
            base[w0 + 128] = f2tf32(v2); base[w0 + 144] = f2tf32(v3);
        }
    }
}

// ---------------- 3. Flash attention, tf32 mma, copy-only loaders ----------
// BM=128 (8 warps), BN=64, 256 threads.
// smem: Qp 16384w, Kp 8192w, Vp 8192w, Ps 128*72=9216w  -> 167936 B
__global__ __launch_bounds__(256) void attn_kernel() {
    extern __shared__ uint32_t smu[];
    uint32_t* Qp = smu;
    uint32_t* Kp = smu + 16384;
    uint32_t* Vp = Kp + 8192;
    uint32_t* Ps = Vp + 8192;
    int tid  = threadIdx.x;
    int wid  = tid >> 5, lane = tid & 31;
    int r    = lane >> 2, cq = lane & 3;
    int bh   = blockIdx.y;
    int m0w  = wid * 16;

    // Q tile: pure copy
    {
        const uint4* Qg = (const uint4*)((const uint32_t*)g_q
                          + ((size_t)bh*16 + blockIdx.x)*16384);
        uint4* Qp4 = (uint4*)Qp;
        for (int i = tid; i < 4096; i += 256) Qp4[i] = Qg[i];
    }

    float oacc[16][4];
    float mprev0 = -INFINITY, mprev1 = -INFINITY, l0 = 0.f, l1 = 0.f;
#pragma unroll
    for (int nf = 0; nf < 16; nf++)
#pragma unroll
        for (int i = 0; i < 4; i++) oacc[nf][i] = 0.f;

    for (int t = 0; t < 32; t++) {
        __syncthreads();
        // K, V: pure copies
        {
            const uint4* Kg = (const uint4*)((const uint32_t*)g_k
                              + ((size_t)bh*32 + t)*8192);
            const uint4* Vg = (const uint4*)((const uint32_t*)g_v
                              + ((size_t)bh*32 + t)*8192);
            uint4* Kp4 = (uint4*)Kp;
            uint4* Vp4 = (uint4*)Vp;
            for (int i = tid; i < 2048; i += 256) Kp4[i] = Kg[i];
            for (int i = tid; i < 2048; i += 256) Vp4[i] = Vg[i];
        }
        __syncthreads();

        // ---- S = Q @ K^T ----
        float sacc[8][4];
#pragma unroll
        for (int nf = 0; nf < 8; nf++)
#pragma unroll
            for (int i = 0; i < 4; i++) sacc[nf][i] = 0.f;
#pragma unroll
        for (int ks = 0; ks < 16; ks++) {
            uint4 A = ((const uint4*)Qp)[(wid*16 + ks)*32 + lane];
#pragma unroll
            for (int p = 0; p < 4; p++) {
                uint4 B = ((const uint4*)Kp)[(p*16 + ks)*32 + lane];
                mma_tf32(sacc[2*p    ], A.x, A.y, A.z, A.w, B.x, B.y);
                mma_tf32(sacc[2*p + 1], A.x, A.y, A.z, A.w, B.z, B.w);
            }
        }

        // ---- online softmax ----
        float mx0 = -INFINITY, mx1 = -INFINITY;
#pragma unroll
        for (int nf = 0; nf < 8; nf++) {
            mx0 = fmaxf(mx0, fmaxf(sacc[nf][0], sacc[nf][1]));
            mx1 = fmaxf(mx1, fmaxf(sacc[nf][2], sacc[nf][3]));
        }
        mx0 = fmaxf(mx0, __shfl_xor_sync(0xffffffffu, mx0, 1));
        mx0 = fmaxf(mx0, __shfl_xor_sync(0xffffffffu, mx0, 2));
        mx1 = fmaxf(mx1, __shfl_xor_sync(0xffffffffu, mx1, 1));
        mx1 = fmaxf(mx1, __shfl_xor_sync(0xffffffffu, mx1, 2));
        float mn0 = fmaxf(mprev0, mx0), mn1 = fmaxf(mprev1, mx1);
        float al0 = __expf(mprev0 - mn0), al1 = __expf(mprev1 - mn1);
        float ps0 = 0.f, ps1 = 0.f;
#pragma unroll
        for (int nf = 0; nf < 8; nf++) {
            float p00 = __expf(sacc[nf][0] - mn0);
            float p01 = __expf(sacc[nf][1] - mn0);
            float p10 = __expf(sacc[nf][2] - mn1);
            float p11 = __expf(sacc[nf][3] - mn1);
            ps0 += p00 + p01;  ps1 += p10 + p11;
            *(uint2*)&Ps[(m0w + r     )*72 + nf*8 + 2*cq] =
                make_uint2(f2tf32(p00), f2tf32(p01));
            *(uint2*)&Ps[(m0w + r + 8 )*72 + nf*8 + 2*cq] =
                make_uint2(f2tf32(p10), f2tf32(p11));
        }
        ps0 += __shfl_xor_sync(0xffffffffu, ps0, 1);
        ps0 += __shfl_xor_sync(0xffffffffu, ps0, 2);
        ps1 += __shfl_xor_sync(0xffffffffu, ps1, 1);
        ps1 += __shfl_xor_sync(0xffffffffu, ps1, 2);
        l0 = l0*al0 + ps0;  l1 = l1*al1 + ps1;
        mprev0 = mn0;       mprev1 = mn1;
#pragma unroll
        for (int nf = 0; nf < 16; nf++) {
            oacc[nf][0] *= al0; oacc[nf][1] *= al0;
            oacc[nf][2] *= al1; oacc[nf][3] *= al1;
        }
        __syncwarp();

        // ---- O += P @ V ----
#pragma unroll
        for (int ks = 0; ks < 8; ks++) {
            int k0 = ks * 8;
            uint32_t a0 = Ps[(m0w + r    )*72 + k0 + cq];
            uint32_t a1 = Ps[(m0w + r + 8)*72 + k0 + cq];
            uint32_t a2 = Ps[(m0w + r    )*72 + k0 + cq + 4];
            uint32_t a3 = Ps[(m0w + r + 8)*72 + k0 + cq + 4];
#pragma unroll
            for (int p = 0; p < 8; p++) {
                uint4 B = ((const uint4*)Vp)[(p*8 + ks)*32 + lane];
                mma_tf32(oacc[2*p    ], a0, a1, a2, a3, B.x, B.y);
                mma_tf32(oacc[2*p + 1], a0, a1, a2, a3, B.z, B.w);
            }
        }
    }
    // ---- epilogue: write permuted g_o (for outproj A-frags) ----
    float inv0 = 1.f / l0, inv1 = 1.f / l1;
    int b  = bh >> 3, h = bh & 7;
    int row_lo = b*2048 + blockIdx.x*128 + wid*16 + r;
    int mb = row_lo >> 6;
    uint32_t* OG = (uint32_t*)g_o;
#pragma unroll
    for (int nf = 0; nf < 16; nf++) {
        int d  = nf*8 + 2*cq;
        int kc = h*2 + (d >> 6);
        int ks = (d >> 3) & 7, cqa = d & 3, half = (d & 7) >> 2;
        size_t base = ((size_t)mb*16 + kc)*4096;
        int w0 = (((wid & 3)*8 + ks)*32 + r*4 + cqa)*4 + (half << 1);
        OG[base + w0    ] = f2tf32(oacc[nf][0]*inv0);
        OG[base + w0 + 4] = f2tf32(oacc[nf][1]*inv0);
        OG[base + w0 + 1] = f2tf32(oacc[nf][2]*inv1);
        OG[base + w0 + 5] = f2tf32(oacc[nf][3]*inv1);
    }
}

// ---------------- 4. Out projection, tf32 mma ------------------------------
// BM=64 (4 warps), N=128, K=1024 in 16 chunks.
__global__ __launch_bounds__(128) void outproj_kernel(const float* __restrict__ w_out,
                                                      const float* __restrict__ b_out,
                                                      float* __restrict__ out) {
    extern __shared__ uint32_t smu[];
    uint32_t* Ap = smu;           // 4096 w
    uint32_t* Bp = smu + 4096;    // 8192 w
    int tid = threadIdx.x, wid = tid >> 5, lane = tid & 31;
    int r = lane >> 2, cq = lane & 3;
    int mb = blockIdx.x;

    float acc[16][4];
#pragma unroll
    for (int nf = 0; nf < 16; nf++)
#pragma unroll
        for (int i = 0; i < 4; i++) acc[nf][i] = 0.f;

    for (int kc = 0; kc < 16; kc++) {
        __syncthreads();
        {
            const uint4* Ag = (const uint4*)((const uint32_t*)g_o
                              + ((size_t)mb*16 + kc)*4096);
            uint4* Ap4 = (uint4*)Ap;
            for (int i = tid; i < 1024; i += 128) Ap4[i] = Ag[i];
        }
        for (int g = tid; g < 2048; g += 128) {
            int pair = g >> 8, ks = (g >> 5) & 7, lt = g & 31;
            int rr = lt >> 2, ca = lt & 3;
            int nrow = pair*16 + rr;
            int c = kc*64 + ks*8 + ca;
            uint4 u;
            u.x = f2tf32(w_out[(size_t)nrow*1024 + c]);
            u.y = f2tf32(w_out[(size_t)nrow*1024 + c + 4]);
            u.z = f2tf32(w_out[(size_t)(nrow+8)*1024 + c]);
            u.w = f2tf32(w_out[(size_t)(nrow+8)*1024 + c + 4]);
            ((uint4*)Bp)[g] = u;
        }
        __syncthreads();
#pragma unroll
        for (int ks = 0; ks < 8; ks++) {
            uint4 A = ((const uint4*)Ap)[(wid*8 + ks)*32 + lane];
#pragma unroll
            for (int p = 0; p < 8; p++) {
                uint4 B = ((const uint4*)Bp)[(p*8 + ks)*32 + lane];
                mma_tf32(acc[2*p    ], A.x, A.y, A.z, A.w, B.x, B.y);
                mma_tf32(acc[2*p + 1], A.x, A.y, A.z, A.w, B.z, B.w);
            }
        }
    }
#pragma unroll
    for (int nf = 0; nf < 16; nf++) {
        int col = nf*8 + 2*cq;
        float b0 = b_out[col], b1 = b_out[col + 1];
        int mlo = mb*64 + wid*16 + r;
        *(float2*)&out[(size_t)mlo*128 + col] =
            make_float2(acc[nf][0] + b0, acc[nf][1] + b1);
        *(float2*)&out[(size_t)(mlo + 8)*128 + col] =
            make_float2(acc[nf][2] + b0, acc[nf][3] + b1);
    }
}

// ---------------- launcher -------------------------------------------------
extern "C" void kernel_launch(void* const* d_in, const int* in_sizes, int n_in,
                              void* d_out, int out_size) {
    const float* x      = (const float*)d_in[0];
    const float* gamma  = (const float*)d_in[1];
    const float* beta   = (const float*)d_in[2];
    const float* w_qkv  = (const float*)d_in[3];
    const float* w_out  = (const float*)d_in[4];
    const float* b_out  = (const float*)d_in[5];
    float* out = (float*)d_out;

    init_invf<<<1, 64>>>();
    ln_kernel<<<1024, 256>>>(x, gamma, beta);

    cudaFuncSetAttribute(qkv_kernel, cudaFuncAttributeMaxDynamicSharedMemorySize, 98304);
    qkv_kernel<<<dim3(48, 64), 256, 98304>>>(w_qkv);

    cudaFuncSetAttribute(attn_kernel, cudaFuncAttributeMaxDynamicSharedMemorySize, 167936);
    attn_kernel<<<dim3(16, 32), 256, 167936>>>();

    cudaFuncSetAttribute(outproj_kernel, cudaFuncAttributeMaxDynamicSharedMemorySize, 49152);
    outproj_kernel<<<128, 128, 49152>>>(w_out, b_out, out);
}

// round 7
// speedup vs baseline: 7.6266x; 1.4064x over previous
#include <cuda_runtime.h>
#include <math.h>
#include <stdint.h>

#define SEQ   2048
#define NB    4
#define NH    8
#define HD    128
#define ROWS  (NB*SEQ)          // 8192

// ---------------- scratch (all fragment-permuted, tf32 bits) ---------------
// g_xn : per 128-row block: [wq8][ks16][lane32][reg4]            (16384 w/blk)
// g_q  : per (bh, 128-row qblock): [wq8][ks16][lane32][reg4]     (16384 w/blk)
// g_k  : per (bh, 64-row kblock):  [pair4][ks16][lane32][reg4]   ( 8192 w/blk)
// g_v  : per (bh, 64-row kblock):  [pair8][ks8][lane32][reg4]    ( 8192 w/blk)
// g_o  : per (64-row mblock, 64-col kchunk): [wq4][ks8][lane32][reg4] (4096 w)
__device__ float g_xn[ROWS*128];
__device__ float g_q[NB*NH*SEQ*HD];
__device__ float g_k[NB*NH*SEQ*HD];
__device__ float g_v[NB*NH*SEQ*HD];
__device__ float g_o[NB*NH*SEQ*HD];
__device__ float g_invf[64];

// ---------------- helpers ----------------
__device__ __forceinline__ uint32_t f2tf32(float f) {
    uint32_t u;
    asm("cvt.rna.tf32.f32 %0, %1;" : "=r"(u) : "f"(f));
    return u;
}
__device__ __forceinline__ void mma_tf32(float* c,
        uint32_t a0, uint32_t a1, uint32_t a2, uint32_t a3,
        uint32_t b0, uint32_t b1) {
    asm volatile("mma.sync.aligned.m16n8k8.row.col.f32.tf32.tf32.f32 "
        "{%0,%1,%2,%3}, {%4,%5,%6,%7}, {%8,%9}, {%0,%1,%2,%3};"
        : "+f"(c[0]), "+f"(c[1]), "+f"(c[2]), "+f"(c[3])
        : "r"(a0), "r"(a1), "r"(a2), "r"(a3), "r"(b0), "r"(b1));
}
__device__ __forceinline__ float fast_ex2(float x) {
    float y;
    asm("ex2.approx.f32 %0, %1;" : "=f"(y) : "f"(x));
    return y;
}
__device__ __forceinline__ void cp_async16(uint32_t saddr, const void* gptr) {
    asm volatile("cp.async.cg.shared.global [%0], [%1], 16;"
                 :: "r"(saddr), "l"(gptr));
}

// ---------------- 0. inv_freq table ----------------------------------------
__global__ void init_invf() {
    int j = threadIdx.x;
    g_invf[j] = (float)pow(10000.0, -((double)(2*j) / 128.0));
}

// ---------------- 1. LayerNorm -> permuted tf32 g_xn ------------------------
__global__ void ln_kernel(const float* __restrict__ x,
                          const float* __restrict__ gamma,
                          const float* __restrict__ beta) {
    int row  = blockIdx.x * 8 + (threadIdx.x >> 5);
    int lane = threadIdx.x & 31;
    float4 v = ((const float4*)(x + (size_t)row * 128))[lane];
    float s  = v.x + v.y + v.z + v.w;
    float s2 = v.x*v.x + v.y*v.y + v.z*v.z + v.w*v.w;
#pragma unroll
    for (int m = 16; m; m >>= 1) {
        s  += __shfl_xor_sync(0xffffffffu, s,  m);
        s2 += __shfl_xor_sync(0xffffffffu, s2, m);
    }
    float mean = s * (1.f/128.f);
    float var  = s2 * (1.f/128.f) - mean*mean;
    float rs   = rsqrtf(var + 1e-5f);
    float4 g = ((const float4*)gamma)[lane];
    float4 b = ((const float4*)beta)[lane];
    float o0 = (v.x-mean)*rs*g.x + b.x;
    float o1 = (v.y-mean)*rs*g.y + b.y;
    float o2 = (v.z-mean)*rs*g.z + b.z;
    float o3 = (v.w-mean)*rs*g.w + b.w;
    uint32_t* dst = (uint32_t*)g_xn + (size_t)(row >> 7)*16384;
    int rl  = row & 127;
    int wq  = rl >> 4, rr = rl & 7, a01 = (rl >> 3) & 1;
    int wbase = ((wq*16 + (lane >> 1))*32 + rr*4)*4 + ((lane & 1) << 1) + a01;
    dst[wbase     ] = f2tf32(o0);
    dst[wbase + 4 ] = f2tf32(o1);
    dst[wbase + 8 ] = f2tf32(o2);
    dst[wbase + 12] = f2tf32(o3);
}

// ---------------- 2. QKV GEMM, tf32 mma, fused RoPE+scale ------------------
__global__ __launch_bounds__(256) void qkv_kernel(const float* __restrict__ w) {
    extern __shared__ uint32_t smu[];
    uint32_t* Ap = smu;            // 16384 w
    uint32_t* Bp = smu + 16384;    // 8192 w
    int tid = threadIdx.x, wid = tid >> 5, lane = tid & 31;
    int r = lane >> 2, cq = lane & 3;
    int n0 = blockIdx.x * 64, m0 = blockIdx.y * 128;

    {
        const uint4* Ag = (const uint4*)((const uint32_t*)g_xn + (size_t)blockIdx.y*16384);
        uint4* Ap4 = (uint4*)Ap;
        for (int i = tid; i < 4096; i += 256) Ap4[i] = Ag[i];
    }
    for (int g = tid; g < 2048; g += 256) {
        int pair = g >> 9, ks = (g >> 5) & 15, lt = g & 31;
        int rr = lt >> 2, ca = lt & 3;
        int rowb = n0 + pair*16 + rr;
        int col  = ks*8 + ca;
        uint4 u;
        u.x = f2tf32(w[(size_t)rowb*128 + col]);
        u.y = f2tf32(w[(size_t)rowb*128 + col + 4]);
        u.z = f2tf32(w[(size_t)(rowb+8)*128 + col]);
        u.w = f2tf32(w[(size_t)(rowb+8)*128 + col + 4]);
        ((uint4*)Bp)[g] = u;
    }
    __syncthreads();

    float acc[8][4];
#pragma unroll
    for (int nf = 0; nf < 8; nf++)
#pragma unroll
        for (int i = 0; i < 4; i++) acc[nf][i] = 0.f;
#pragma unroll
    for (int ks = 0; ks < 16; ks++) {
        uint4 A = ((const uint4*)Ap)[(wid*16 + ks)*32 + lane];
#pragma unroll
        for (int p = 0; p < 4; p++) {
            uint4 B = ((const uint4*)Bp)[(p*16 + ks)*32 + lane];
            mma_tf32(acc[2*p    ], A.x, A.y, A.z, A.w, B.x, B.y);
            mma_tf32(acc[2*p + 1], A.x, A.y, A.z, A.w, B.z, B.w);
        }
    }

    // ---- epilogue: rope (+scale*log2e for q), scatter to permuted global ----
    int part = n0 >> 10;                      // 0=q 1=k 2=v
    const float qscale = 0.08838834764831845f * 1.44269504088896340736f;
    int m_lo = m0 + wid*16 + r;
    int b_   = m_lo >> 11;
    int n_lo = m_lo & 2047;
    int n_hi = n_lo + 8;
#pragma unroll
    for (int nf = 0; nf < 8; nf++) {
        int e = n0 + nf*8 + 2*cq;
        int h = (e & 1023) >> 7;
        int d = e & 127;
        float v0 = acc[nf][0], v1 = acc[nf][1];
        float v2 = acc[nf][2], v3 = acc[nf][3];
        if (part < 2) {
            float invf = g_invf[d >> 1];
            if (n_lo < 2047) {
                float sn, cs; sincosf((float)n_lo * invf, &sn, &cs);
                float t0 = v0*cs - v1*sn; v1 = v1*cs + v0*sn; v0 = t0;
            }
            if (n_hi < 2047) {
                float sn, cs; sincosf((float)n_hi * invf, &sn, &cs);
                float t2 = v2*cs - v3*sn; v3 = v3*cs + v2*sn; v2 = t2;
            }
            if (part == 0) { v0*=qscale; v1*=qscale; v2*=qscale; v3*=qscale; }
        }
        int bh_ = b_*8 + h;
        if (part == 0) {
            uint32_t* base = (uint32_t*)g_q + ((size_t)bh_*16 + (n_lo >> 7))*16384;
            int w0 = ((wid*16 + (d >> 3))*32 + r*4 + (d & 3))*4 + (((d & 7) >> 2) << 1);
            base[w0    ] = f2tf32(v0); base[w0 + 4] = f2tf32(v1);
            base[w0 + 1] = f2tf32(v2); base[w0 + 5] = f2tf32(v3);
        } else if (part == 1) {
            uint32_t* base = (uint32_t*)g_k + ((size_t)bh_*32 + (n_lo >> 6))*8192;
            int pair = wid & 3;
            int w0 = ((pair*16 + (d >> 3))*32 + r*4 + (d & 3))*4 + ((d & 7) >> 2);
            base[w0    ] = f2tf32(v0); base[w0 + 4] = f2tf32(v1);
            base[w0 + 2] = f2tf32(v2); base[w0 + 6] = f2tf32(v3);
        } else {
            uint32_t* base = (uint32_t*)g_v + ((size_t)bh_*32 + (n_lo >> 6))*8192;
            int ks_lo = (wid & 3)*2, half_k = r >> 2, cqv = r & 3;
            int w0 = (((d >> 4)*8 + ks_lo)*32 + (d & 7)*4 + cqv)*4
                     + (((d >> 3) & 1) << 1) + half_k;
            base[w0      ] = f2tf32(v0); base[w0 + 16 ] = f2tf32(v1);
            base[w0 + 128] = f2tf32(v2); base[w0 + 144] = f2tf32(v3);
        }
    }
}

// ---------------- 3. Flash attention: Q in regs, cp.async double buffer ----
// smem: Kp[2] 2x8192w, Vp[2] 2x8192w, Ps 128*72=9216w -> 167936 B
__global__ __launch_bounds__(256) void attn_kernel() {
    extern __shared__ uint32_t smu[];
    // word offsets: K0=0, K1=8192, V0=16384, V1=24576, Ps=32768
    uint32_t* Ps = smu + 32768;
    int tid  = threadIdx.x;
    int wid  = tid >> 5, lane = tid & 31;
    int r    = lane >> 2, cq = lane & 3;
    int bh   = blockIdx.y;
    int m0w  = wid * 16;

    // ---- Q fragments straight to registers (coalesced, permuted layout) ----
    uint4 Qf[16];
    {
        const uint4* Qg = (const uint4*)((const uint32_t*)g_q
                          + ((size_t)bh*16 + blockIdx.x)*16384);
#pragma unroll
        for (int ks = 0; ks < 16; ks++)
            Qf[ks] = Qg[(wid*16 + ks)*32 + lane];
    }

    uint32_t smem_base = (uint32_t)__cvta_generic_to_shared(smu);
    const uint32_t* Kg0 = (const uint32_t*)g_k + (size_t)bh*32*8192;
    const uint32_t* Vg0 = (const uint32_t*)g_v + (size_t)bh*32*8192;

    // prefetch tile 0 into buffer 0
    {
        const uint4* Kg = (const uint4*)Kg0;
        const uint4* Vg = (const uint4*)Vg0;
#pragma unroll
        for (int i = 0; i < 8; i++) {
            int idx = tid + i*256;
            cp_async16(smem_base + idx*16,          Kg + idx);
            cp_async16(smem_base + 65536 + idx*16,  Vg + idx);
        }
        asm volatile("cp.async.commit_group;" ::: "memory");
    }

    float oacc[16][4];
    float mprev0 = -INFINITY, mprev1 = -INFINITY, l0 = 0.f, l1 = 0.f;
#pragma unroll
    for (int nf = 0; nf < 16; nf++)
#pragma unroll
        for (int i = 0; i < 4; i++) oacc[nf][i] = 0.f;

    for (int t = 0; t < 32; t++) {
        int buf = t & 1;
        asm volatile("cp.async.wait_group 0;" ::: "memory");
        __syncthreads();   // data visible; everyone done with buffer buf^1
        if (t + 1 < 32) {
            int nb = buf ^ 1;
            const uint4* Kg = (const uint4*)(Kg0 + (size_t)(t+1)*8192);
            const uint4* Vg = (const uint4*)(Vg0 + (size_t)(t+1)*8192);
#pragma unroll
            for (int i = 0; i < 8; i++) {
                int idx = tid + i*256;
                cp_async16(smem_base + nb*32768 + idx*16,         Kg + idx);
                cp_async16(smem_base + 65536 + nb*32768 + idx*16, Vg + idx);
            }
            asm volatile("cp.async.commit_group;" ::: "memory");
        }
        const uint32_t* Kp = smu + buf*8192;
        const uint32_t* Vp = smu + 16384 + buf*8192;

        // ---- S = Q @ K^T (S in log2 domain: q pre-scaled by scale*log2e) ----
        float sacc[8][4];
#pragma unroll
        for (int nf = 0; nf < 8; nf++)
#pragma unroll
            for (int i = 0; i < 4; i++) sacc[nf][i] = 0.f;
#pragma unroll
        for (int ks = 0; ks < 16; ks++) {
            uint4 A = Qf[ks];
#pragma unroll
            for (int p = 0; p < 4; p++) {
                uint4 B = ((const uint4*)Kp)[(p*16 + ks)*32 + lane];
                mma_tf32(sacc[2*p    ], A.x, A.y, A.z, A.w, B.x, B.y);
                mma_tf32(sacc[2*p + 1], A.x, A.y, A.z, A.w, B.z, B.w);
            }
        }

        // ---- online softmax (base-2) ----
        float mx0 = -INFINITY, mx1 = -INFINITY;
#pragma unroll
        for (int nf = 0; nf < 8; nf++) {
            mx0 = fmaxf(mx0, fmaxf(sacc[nf][0], sacc[nf][1]));
            mx1 = fmaxf(mx1, fmaxf(sacc[nf][2], sacc[nf][3]));
        }
        mx0 = fmaxf(mx0, __shfl_xor_sync(0xffffffffu, mx0, 1));
        mx0 = fmaxf(mx0, __shfl_xor_sync(0xffffffffu, mx0, 2));
        mx1 = fmaxf(mx1, __shfl_xor_sync(0xffffffffu, mx1, 1));
        mx1 = fmaxf(mx1, __shfl_xor_sync(0xffffffffu, mx1, 2));
        float mn0 = fmaxf(mprev0, mx0), mn1 = fmaxf(mprev1, mx1);
        float al0 = fast_ex2(mprev0 - mn0), al1 = fast_ex2(mprev1 - mn1);
        float ps0 = 0.f, ps1 = 0.f;
#pragma unroll
        for (int nf = 0; nf < 8; nf++) {
            float p00 = fast_ex2(sacc[nf][0] - mn0);
            float p01 = fast_ex2(sacc[nf][1] - mn0);
            float p10 = fast_ex2(sacc[nf][2] - mn1);
            float p11 = fast_ex2(sacc[nf][3] - mn1);
            ps0 += p00 + p01;  ps1 += p10 + p11;
            *(uint2*)&Ps[(m0w + r     )*72 + nf*8 + 2*cq] =
                make_uint2(f2tf32(p00), f2tf32(p01));
            *(uint2*)&Ps[(m0w + r + 8 )*72 + nf*8 + 2*cq] =
                make_uint2(f2tf32(p10), f2tf32(p11));
        }
        ps0 += __shfl_xor_sync(0xffffffffu, ps0, 1);
        ps0 += __shfl_xor_sync(0xffffffffu, ps0, 2);
        ps1 += __shfl_xor_sync(0xffffffffu, ps1, 1);
        ps1 += __shfl_xor_sync(0xffffffffu, ps1, 2);
        l0 = l0*al0 + ps0;  l1 = l1*al1 + ps1;
        mprev0 = mn0;       mprev1 = mn1;
#pragma unroll
        for (int nf = 0; nf < 16; nf++) {
            oacc[nf][0] *= al0; oacc[nf][1] *= al0;
            oacc[nf][2] *= al1; oacc[nf][3] *= al1;
        }
        __syncwarp();

        // ---- O += P @ V ----
#pragma unroll
        for (int ks = 0; ks < 8; ks++) {
            int k0 = ks * 8;
            uint32_t a0 = Ps[(m0w + r    )*72 + k0 + cq];
            uint32_t a1 = Ps[(m0w + r + 8)*72 + k0 + cq];
            uint32_t a2 = Ps[(m0w + r    )*72 + k0 + cq + 4];
            uint32_t a3 = Ps[(m0w + r + 8)*72 + k0 + cq + 4];
#pragma unroll
            for (int p = 0; p < 8; p++) {
                uint4 B = ((const uint4*)Vp)[(p*8 + ks)*32 + lane];
                mma_tf32(oacc[2*p    ], a0, a1, a2, a3, B.x, B.y);
                mma_tf32(oacc[2*p + 1], a0, a1, a2, a3, B.z, B.w);
            }
        }
    }
    // ---- epilogue: write permuted g_o (for outproj A-frags) ----
    float inv0 = 1.f / l0, inv1 = 1.f / l1;
    int b  = bh >> 3, h = bh & 7;
    int row_lo = b*2048 + blockIdx.x*128 + wid*16 + r;
    int mb = row_lo >> 6;
    uint32_t* OG = (uint32_t*)g_o;
#pragma unroll
    for (int nf = 0; nf < 16; nf++) {
        int d  = nf*8 + 2*cq;
        int kc = h*2 + (d >> 6);
        int ks = (d >> 3) & 7, cqa = d & 3, half = (d & 7) >> 2;
        size_t base = ((size_t)mb*16 + kc)*4096;
        int w0 = (((wid & 3)*8 + ks)*32 + r*4 + cqa)*4 + (half << 1);
        OG[base + w0    ] = f2tf32(oacc[nf][0]*inv0);
        OG[base + w0 + 4] = f2tf32(oacc[nf][1]*inv0);
        OG[base + w0 + 1] = f2tf32(oacc[nf][2]*inv1);
        OG[base + w0 + 5] = f2tf32(oacc[nf][3]*inv1);
    }
}

// ---------------- 4. Out projection, tf32 mma ------------------------------
__global__ __launch_bounds__(128) void outproj_kernel(const float* __restrict__ w_out,
                                                      const float* __restrict__ b_out,
                                                      float* __restrict__ out) {
    extern __shared__ uint32_t smu[];
    uint32_t* Ap = smu;           // 4096 w
    uint32_t* Bp = smu + 4096;    // 8192 w
    int tid = threadIdx.x, wid = tid >> 5, lane = tid & 31;
    int r = lane >> 2, cq = lane & 3;
    int mb = blockIdx.x;

    float acc[16][4];
#pragma unroll
    for (int nf = 0; nf < 16; nf++)
#pragma unroll
        for (int i = 0; i < 4; i++) acc[nf][i] = 0.f;

    for (int kc = 0; kc < 16; kc++) {
        __syncthreads();
        {
            const uint4* Ag = (const uint4*)((const uint32_t*)g_o
                              + ((size_t)mb*16 + kc)*4096);
            uint4* Ap4 = (uint4*)Ap;
            for (int i = tid; i < 1024; i += 128) Ap4[i] = Ag[i];
        }
        for (int g = tid; g < 2048; g += 128) {
            int pair = g >> 8, ks = (g >> 5) & 7, lt = g & 31;
            int rr = lt >> 2, ca = lt & 3;
            int nrow = pair*16 + rr;
            int c = kc*64 + ks*8 + ca;
            uint4 u;
            u.x = f2tf32(w_out[(size_t)nrow*1024 + c]);
            u.y = f2tf32(w_out[(size_t)nrow*1024 + c + 4]);
            u.z = f2tf32(w_out[(size_t)(nrow+8)*1024 + c]);
            u.w = f2tf32(w_out[(size_t)(nrow+8)*1024 + c + 4]);
            ((uint4*)Bp)[g] = u;
        }
        __syncthreads();
#pragma unroll
        for (int ks = 0; ks < 8; ks++) {
            uint4 A = ((const uint4*)Ap)[(wid*8 + ks)*32 + lane];
#pragma unroll
            for (int p = 0; p < 8; p++) {
                uint4 B = ((const uint4*)Bp)[(p*8 + ks)*32 + lane];
                mma_tf32(acc[2*p    ], A.x, A.y, A.z, A.w, B.x, B.y);
                mma_tf32(acc[2*p + 1], A.x, A.y, A.z, A.w, B.z, B.w);
            }
        }
    }
#pragma unroll
    for (int nf = 0; nf < 16; nf++) {
        int col = nf*8 + 2*cq;
        float b0 = b_out[col], b1 = b_out[col + 1];
        int mlo = mb*64 + wid*16 + r;
        *(float2*)&out[(size_t)mlo*128 + col] =
            make_float2(acc[nf][0] + b0, acc[nf][1] + b1);
        *(float2*)&out[(size_t)(mlo + 8)*128 + col] =
            make_float2(acc[nf][2] + b0, acc[nf][3] + b1);
    }
}

// ---------------- launcher -------------------------------------------------
extern "C" void kernel_launch(void* const* d_in, const int* in_sizes, int n_in,
                              void* d_out, int out_size) {
    const float* x      = (const float*)d_in[0];
    const float* gamma  = (const float*)d_in[1];
    const float* beta   = (const float*)d_in[2];
    const float* w_qkv  = (const float*)d_in[3];
    const float* w_out  = (const float*)d_in[4];
    const float* b_out  = (const float*)d_in[5];
    float* out = (float*)d_out;

    init_invf<<<1, 64>>>();
    ln_kernel<<<1024, 256>>>(x, gamma, beta);

    cudaFuncSetAttribute(qkv_kernel, cudaFuncAttributeMaxDynamicSharedMemorySize, 98304);
    qkv_kernel<<<dim3(48, 64), 256, 98304>>>(w_qkv);

    cudaFuncSetAttribute(attn_kernel, cudaFuncAttributeMaxDynamicSharedMemorySize, 167936);
    attn_kernel<<<dim3(16, 32), 256, 167936>>>();

    cudaFuncSetAttribute(outproj_kernel, cudaFuncAttributeMaxDynamicSharedMemorySize, 49152);
    outproj_kernel<<<128, 128, 49152>>>(w_out, b_out, out);
}

// round 8
// speedup vs baseline: 12.5062x; 1.6398x over previous
#include <cuda_runtime.h>
#include <cuda_fp16.h>
#include <math.h>
#include <stdint.h>

#define SEQ   2048
#define NB    4
#define NH    8
#define HD    128
#define ROWS  (NB*SEQ)          // 8192

// ---------------- scratch ----------------
// g_xn : tf32 permuted (qkv A): per 128-row block [wq8][ks16][lane32][reg4]
// g_q  : fp16 A-frags per (bh, 64-row block):  [w4][ks8][lane32][4 half2] (4096 w)
// g_k  : fp16 B-frags per (bh, 64-key block):  [pair4][ks8][lane32][4]    (4096 w)
// g_v  : fp16 B-frags per (bh, 64-key block):  [pair8][ks4][lane32][4]    (4096 w)
// g_o  : tf32 permuted (outproj A): per (64-row, 64-col) [wq4][ks8][lane32][4]
__device__ float g_xn[ROWS*128];
__device__ float g_q[NB*NH*SEQ*HD/2 + 1024];
__device__ float g_k[NB*NH*SEQ*HD/2 + 1024];
__device__ float g_v[NB*NH*SEQ*HD/2 + 1024];
__device__ float g_o[NB*NH*SEQ*HD];
__device__ float g_invf[64];

// ---------------- helpers ----------------
__device__ __forceinline__ uint32_t f2tf32(float f) {
    uint32_t u;
    asm("cvt.rna.tf32.f32 %0, %1;" : "=r"(u) : "f"(f));
    return u;
}
__device__ __forceinline__ uint32_t pkh2(float lo, float hi) {
    __half2 h = __floats2half2_rn(lo, hi);
    return *(uint32_t*)&h;
}
__device__ __forceinline__ void mma_tf32(float* c,
        uint32_t a0, uint32_t a1, uint32_t a2, uint32_t a3,
        uint32_t b0, uint32_t b1) {
    asm volatile("mma.sync.aligned.m16n8k8.row.col.f32.tf32.tf32.f32 "
        "{%0,%1,%2,%3}, {%4,%5,%6,%7}, {%8,%9}, {%0,%1,%2,%3};"
        : "+f"(c[0]), "+f"(c[1]), "+f"(c[2]), "+f"(c[3])
        : "r"(a0), "r"(a1), "r"(a2), "r"(a3), "r"(b0), "r"(b1));
}
__device__ __forceinline__ void mma_f16(float* c,
        uint32_t a0, uint32_t a1, uint32_t a2, uint32_t a3,
        uint32_t b0, uint32_t b1) {
    asm volatile("mma.sync.aligned.m16n8k16.row.col.f32.f16.f16.f32 "
        "{%0,%1,%2,%3}, {%4,%5,%6,%7}, {%8,%9}, {%0,%1,%2,%3};"
        : "+f"(c[0]), "+f"(c[1]), "+f"(c[2]), "+f"(c[3])
        : "r"(a0), "r"(a1), "r"(a2), "r"(a3), "r"(b0), "r"(b1));
}
__device__ __forceinline__ float fast_ex2(float x) {
    float y;
    asm("ex2.approx.f32 %0, %1;" : "=f"(y) : "f"(x));
    return y;
}
__device__ __forceinline__ void cp_async16(uint32_t saddr, const void* gptr) {
    asm volatile("cp.async.cg.shared.global [%0], [%1], 16;"
                 :: "r"(saddr), "l"(gptr));
}

// ---------------- 0. inv_freq table ----------------------------------------
__global__ void init_invf() {
    int j = threadIdx.x;
    g_invf[j] = (float)pow(10000.0, -((double)(2*j) / 128.0));
}

// ---------------- 1. LayerNorm -> permuted tf32 g_xn ------------------------
__global__ void ln_kernel(const float* __restrict__ x,
                          const float* __restrict__ gamma,
                          const float* __restrict__ beta) {
    int row  = blockIdx.x * 8 + (threadIdx.x >> 5);
    int lane = threadIdx.x & 31;
    float4 v = ((const float4*)(x + (size_t)row * 128))[lane];
    float s  = v.x + v.y + v.z + v.w;
    float s2 = v.x*v.x + v.y*v.y + v.z*v.z + v.w*v.w;
#pragma unroll
    for (int m = 16; m; m >>= 1) {
        s  += __shfl_xor_sync(0xffffffffu, s,  m);
        s2 += __shfl_xor_sync(0xffffffffu, s2, m);
    }
    float mean = s * (1.f/128.f);
    float var  = s2 * (1.f/128.f) - mean*mean;
    float rs   = rsqrtf(var + 1e-5f);
    float4 g = ((const float4*)gamma)[lane];
    float4 b = ((const float4*)beta)[lane];
    float o0 = (v.x-mean)*rs*g.x + b.x;
    float o1 = (v.y-mean)*rs*g.y + b.y;
    float o2 = (v.z-mean)*rs*g.z + b.z;
    float o3 = (v.w-mean)*rs*g.w + b.w;
    uint32_t* dst = (uint32_t*)g_xn + (size_t)(row >> 7)*16384;
    int rl  = row & 127;
    int wq  = rl >> 4, rr = rl & 7, a01 = (rl >> 3) & 1;
    int wbase = ((wq*16 + (lane >> 1))*32 + rr*4)*4 + ((lane & 1) << 1) + a01;
    dst[wbase     ] = f2tf32(o0);
    dst[wbase + 4 ] = f2tf32(o1);
    dst[wbase + 8 ] = f2tf32(o2);
    dst[wbase + 12] = f2tf32(o3);
}

// ---------------- 2. QKV GEMM (tf32 mma) + fused RoPE, fp16 frag output ----
__global__ __launch_bounds__(256) void qkv_kernel(const float* __restrict__ w) {
    extern __shared__ uint32_t smu[];
    uint32_t* Ap = smu;            // 16384 w
    uint32_t* Bp = smu + 16384;    // 8192 w
    int tid = threadIdx.x, wid = tid >> 5, lane = tid & 31;
    int r = lane >> 2, cq = lane & 3;
    int n0 = blockIdx.x * 64, m0 = blockIdx.y * 128;

    {
        const uint4* Ag = (const uint4*)((const uint32_t*)g_xn + (size_t)blockIdx.y*16384);
        uint4* Ap4 = (uint4*)Ap;
        for (int i = tid; i < 4096; i += 256) Ap4[i] = Ag[i];
    }
    for (int g = tid; g < 2048; g += 256) {
        int pair = g >> 9, ks = (g >> 5) & 15, lt = g & 31;
        int rr = lt >> 2, ca = lt & 3;
        int rowb = n0 + pair*16 + rr;
        int col  = ks*8 + ca;
        uint4 u;
        u.x = f2tf32(w[(size_t)rowb*128 + col]);
        u.y = f2tf32(w[(size_t)rowb*128 + col + 4]);
        u.z = f2tf32(w[(size_t)(rowb+8)*128 + col]);
        u.w = f2tf32(w[(size_t)(rowb+8)*128 + col + 4]);
        ((uint4*)Bp)[g] = u;
    }
    __syncthreads();

    float acc[8][4];
#pragma unroll
    for (int nf = 0; nf < 8; nf++)
#pragma unroll
        for (int i = 0; i < 4; i++) acc[nf][i] = 0.f;
#pragma unroll
    for (int ks = 0; ks < 16; ks++) {
        uint4 A = ((const uint4*)Ap)[(wid*16 + ks)*32 + lane];
#pragma unroll
        for (int p = 0; p < 4; p++) {
            uint4 B = ((const uint4*)Bp)[(p*16 + ks)*32 + lane];
            mma_tf32(acc[2*p    ], A.x, A.y, A.z, A.w, B.x, B.y);
            mma_tf32(acc[2*p + 1], A.x, A.y, A.z, A.w, B.z, B.w);
        }
    }

    // ---- epilogue: rope (+scale*log2e for q), pack fp16 frags -------------
    int part = n0 >> 10;                      // 0=q 1=k 2=v
    const float qscale = 0.08838834764831845f * 1.44269504088896340736f;
    int m_lo = m0 + wid*16 + r;
    int b_   = m_lo >> 11;
    int n_lo = m_lo & 2047;
    int n_hi = n_lo + 8;
    int bh_  = b_*8;   // +h below
    int wq4  = wid & 3;
#pragma unroll
    for (int nf = 0; nf < 8; nf++) {
        int e = n0 + nf*8 + 2*cq;
        int h = (e & 1023) >> 7;
        int d = e & 127;
        float v0 = acc[nf][0], v1 = acc[nf][1];    // (row n_lo, d), (n_lo, d+1)
        float v2 = acc[nf][2], v3 = acc[nf][3];    // (row n_hi, ...)
        if (part < 2) {
            float invf = g_invf[d >> 1];
            if (n_lo < 2047) {
                float sn, cs; sincosf((float)n_lo * invf, &sn, &cs);
                float t0 = v0*cs - v1*sn; v1 = v1*cs + v0*sn; v0 = t0;
            }
            if (n_hi < 2047) {
                float sn, cs; sincosf((float)n_hi * invf, &sn, &cs);
                float t2 = v2*cs - v3*sn; v3 = v3*cs + v2*sn; v2 = t2;
            }
            if (part == 0) { v0*=qscale; v1*=qscale; v2*=qscale; v3*=qscale; }
        }
        int blk = (bh_ + h)*32 + (n_lo >> 6);
        int ks  = d >> 4, hi = (d >> 3) & 1;
        if (part == 0) {
            uint32_t* base = (uint32_t*)g_q + (size_t)blk*4096;
            int w0 = ((wq4*8 + ks)*32 + lane)*4 + 2*hi;
            base[w0    ] = pkh2(v0, v1);     // a0/a2 (row r)
            base[w0 + 1] = pkh2(v2, v3);     // a1/a3 (row r+8)
        } else if (part == 1) {
            uint32_t* base = (uint32_t*)g_k + (size_t)blk*4096;
            int w0 = ((wq4*8 + ks)*32 + lane)*4 + hi;
            base[w0    ] = pkh2(v0, v1);     // nf-even (key n_lo)
            base[w0 + 2] = pkh2(v2, v3);     // nf-odd  (key n_hi)
        } else {
            __half* base = (__half*)((uint32_t*)g_v + (size_t)blk*4096);
            int pair = d >> 4, hn = (d >> 3) & 1;
            int lane0 = 4*(d & 7) + (r >> 1);
            int w0 = ((pair*4 + wq4)*32 + lane0)*4 + 2*hn;       // b0, col d
            int w1 = w0 + 16;                                     // col d+1 (+4 lanes)
            int hf = r & 1;
            base[(w0    )*2 + hf] = __float2half(v0);
            base[(w1    )*2 + hf] = __float2half(v1);
            base[(w0 + 1)*2 + hf] = __float2half(v2);   // b1: key +8
            base[(w1 + 1)*2 + hf] = __float2half(v3);
        }
    }
}

// ---------------- 3. Flash attention fp16 mma, BM=64, no P round-trip ------
// smem words: K0=0, K1=4096, V0=8192, V1=12288  -> 65536 B, 2-3 CTAs/SM
__global__ __launch_bounds__(128) void attn_kernel() {
    extern __shared__ uint32_t smu[];
    int tid  = threadIdx.x;
    int wid  = tid >> 5, lane = tid & 31;
    int r    = lane >> 2, cq = lane & 3;
    int bh   = blockIdx.y;

    // Q fragments -> registers (coalesced from permuted fp16 g_q)
    uint4 Qf[8];
    {
        const uint4* Qg = (const uint4*)((const uint32_t*)g_q
                          + ((size_t)bh*32 + blockIdx.x)*4096);
#pragma unroll
        for (int ks = 0; ks < 8; ks++)
            Qf[ks] = Qg[(wid*8 + ks)*32 + lane];
    }

    uint32_t smem_base = (uint32_t)__cvta_generic_to_shared(smu);
    const uint32_t* Kg0 = (const uint32_t*)g_k + (size_t)bh*32*4096;
    const uint32_t* Vg0 = (const uint32_t*)g_v + (size_t)bh*32*4096;

    // prefetch tile 0 -> buffer 0
    {
        const uint4* Kg = (const uint4*)Kg0;
        const uint4* Vg = (const uint4*)Vg0;
#pragma unroll
        for (int i = 0; i < 8; i++) {
            int idx = tid + i*128;
            cp_async16(smem_base + idx*16,          Kg + idx);
            cp_async16(smem_base + 32768 + idx*16,  Vg + idx);
        }
        asm volatile("cp.async.commit_group;" ::: "memory");
    }

    float oacc[16][4];
    float mprev0 = -INFINITY, mprev1 = -INFINITY, l0 = 0.f, l1 = 0.f;
#pragma unroll
    for (int nf = 0; nf < 16; nf++)
#pragma unroll
        for (int i = 0; i < 4; i++) oacc[nf][i] = 0.f;

    for (int t = 0; t < 32; t++) {
        int buf = t & 1;
        asm volatile("cp.async.wait_group 0;" ::: "memory");
        __syncthreads();
        if (t + 1 < 32) {
            int nb = buf ^ 1;
            const uint4* Kg = (const uint4*)(Kg0 + (size_t)(t+1)*4096);
            const uint4* Vg = (const uint4*)(Vg0 + (size_t)(t+1)*4096);
#pragma unroll
            for (int i = 0; i < 8; i++) {
                int idx = tid + i*128;
                cp_async16(smem_base + nb*16384 + idx*16,         Kg + idx);
                cp_async16(smem_base + 32768 + nb*16384 + idx*16, Vg + idx);
            }
            asm volatile("cp.async.commit_group;" ::: "memory");
        }
        const uint32_t* Kp = smu + buf*4096;
        const uint32_t* Vp = smu + 8192 + buf*4096;

        // ---- S = Q @ K^T (fp16 k16; S in log2 domain) ----
        float sacc[8][4];
#pragma unroll
        for (int nf = 0; nf < 8; nf++)
#pragma unroll
            for (int i = 0; i < 4; i++) sacc[nf][i] = 0.f;
#pragma unroll
        for (int ks = 0; ks < 8; ks++) {
            uint4 A = Qf[ks];
#pragma unroll
            for (int p = 0; p < 4; p++) {
                uint4 B = ((const uint4*)Kp)[(p*8 + ks)*32 + lane];
                mma_f16(sacc[2*p    ], A.x, A.y, A.z, A.w, B.x, B.y);
                mma_f16(sacc[2*p + 1], A.x, A.y, A.z, A.w, B.z, B.w);
            }
        }

        // ---- online softmax (base-2), P packed to fp16 in registers ----
        float mx0 = -INFINITY, mx1 = -INFINITY;
#pragma unroll
        for (int nf = 0; nf < 8; nf++) {
            mx0 = fmaxf(mx0, fmaxf(sacc[nf][0], sacc[nf][1]));
            mx1 = fmaxf(mx1, fmaxf(sacc[nf][2], sacc[nf][3]));
        }
        mx0 = fmaxf(mx0, __shfl_xor_sync(0xffffffffu, mx0, 1));
        mx0 = fmaxf(mx0, __shfl_xor_sync(0xffffffffu, mx0, 2));
        mx1 = fmaxf(mx1, __shfl_xor_sync(0xffffffffu, mx1, 1));
        mx1 = fmaxf(mx1, __shfl_xor_sync(0xffffffffu, mx1, 2));
        float mn0 = fmaxf(mprev0, mx0), mn1 = fmaxf(mprev1, mx1);
        float al0 = fast_ex2(mprev0 - mn0), al1 = fast_ex2(mprev1 - mn1);
        float ps0 = 0.f, ps1 = 0.f;
        uint32_t ph[8][2];
#pragma unroll
        for (int nf = 0; nf < 8; nf++) {
            float p00 = fast_ex2(sacc[nf][0] - mn0);
            float p01 = fast_ex2(sacc[nf][1] - mn0);
            float p10 = fast_ex2(sacc[nf][2] - mn1);
            float p11 = fast_ex2(sacc[nf][3] - mn1);
            ps0 += p00 + p01;  ps1 += p10 + p11;
            ph[nf][0] = pkh2(p00, p01);   // row r
            ph[nf][1] = pkh2(p10, p11);   // row r+8
        }
        ps0 += __shfl_xor_sync(0xffffffffu, ps0, 1);
        ps0 += __shfl_xor_sync(0xffffffffu, ps0, 2);
        ps1 += __shfl_xor_sync(0xffffffffu, ps1, 1);
        ps1 += __shfl_xor_sync(0xffffffffu, ps1, 2);
        l0 = l0*al0 + ps0;  l1 = l1*al1 + ps1;
        mprev0 = mn0;       mprev1 = mn1;
#pragma unroll
        for (int nf = 0; nf < 16; nf++) {
            oacc[nf][0] *= al0; oacc[nf][1] *= al0;
            oacc[nf][2] *= al1; oacc[nf][3] *= al1;
        }

        // ---- O += P @ V (A-frag = packed C-frag pairs; no smem) ----
#pragma unroll
        for (int ks = 0; ks < 4; ks++) {
            uint32_t a0 = ph[2*ks    ][0];
            uint32_t a1 = ph[2*ks    ][1];
            uint32_t a2 = ph[2*ks + 1][0];
            uint32_t a3 = ph[2*ks + 1][1];
#pragma unroll
            for (int p = 0; p < 8; p++) {
                uint4 B = ((const uint4*)Vp)[(p*4 + ks)*32 + lane];
                mma_f16(oacc[2*p    ], a0, a1, a2, a3, B.x, B.y);
                mma_f16(oacc[2*p + 1], a0, a1, a2, a3, B.z, B.w);
            }
        }
    }
    // ---- epilogue: write permuted tf32 g_o (outproj A-frags) ----
    float inv0 = 1.f / l0, inv1 = 1.f / l1;
    int b  = bh >> 3, h = bh & 7;
    int row_lo = b*2048 + blockIdx.x*64 + wid*16 + r;
    int mb = row_lo >> 6;
    uint32_t* OG = (uint32_t*)g_o;
#pragma unroll
    for (int nf = 0; nf < 16; nf++) {
        int d  = nf*8 + 2*cq;
        int kc = h*2 + (d >> 6);
        int ks = (d >> 3) & 7, cqa = d & 3, half = (d & 7) >> 2;
        size_t base = ((size_t)mb*16 + kc)*4096;
        int w0 = ((wid*8 + ks)*32 + r*4 + cqa)*4 + (half << 1);
        OG[base + w0    ] = f2tf32(oacc[nf][0]*inv0);
        OG[base + w0 + 4] = f2tf32(oacc[nf][1]*inv0);
        OG[base + w0 + 1] = f2tf32(oacc[nf][2]*inv1);
        OG[base + w0 + 5] = f2tf32(oacc[nf][3]*inv1);
    }
}

// ---------------- 4. Out projection, tf32 mma ------------------------------
__global__ __launch_bounds__(128) void outproj_kernel(const float* __restrict__ w_out,
                                                      const float* __restrict__ b_out,
                                                      float* __restrict__ out) {
    extern __shared__ uint32_t smu[];
    uint32_t* Ap = smu;           // 4096 w
    uint32_t* Bp = smu + 4096;    // 8192 w
    int tid = threadIdx.x, wid = tid >> 5, lane = tid & 31;
    int r = lane >> 2, cq = lane & 3;
    int mb = blockIdx.x;

    float acc[16][4];
#pragma unroll
    for (int nf = 0; nf < 16; nf++)
#pragma unroll
        for (int i = 0; i < 4; i++) acc[nf][i] = 0.f;

    for (int kc = 0; kc < 16; kc++) {
        __syncthreads();
        {
            const uint4* Ag = (const uint4*)((const uint32_t*)g_o
                              + ((size_t)mb*16 + kc)*4096);
            uint4* Ap4 = (uint4*)Ap;
            for (int i = tid; i < 1024; i += 128) Ap4[i] = Ag[i];
        }
        for (int g = tid; g < 2048; g += 128) {
            int pair = g >> 8, ks = (g >> 5) & 7, lt = g & 31;
            int rr = lt >> 2, ca = lt & 3;
            int nrow = pair*16 + rr;
            int c = kc*64 + ks*8 + ca;
            uint4 u;
            u.x = f2tf32(w_out[(size_t)nrow*1024 + c]);
            u.y = f2tf32(w_out[(size_t)nrow*1024 + c + 4]);
            u.z = f2tf32(w_out[(size_t)(nrow+8)*1024 + c]);
            u.w = f2tf32(w_out[(size_t)(nrow+8)*1024 + c + 4]);
            ((uint4*)Bp)[g] = u;
        }
        __syncthreads();
#pragma unroll
        for (int ks = 0; ks < 8; ks++) {
            uint4 A = ((const uint4*)Ap)[(wid*8 + ks)*32 + lane];
#pragma unroll
            for (int p = 0; p < 8; p++) {
                uint4 B = ((const uint4*)Bp)[(p*8 + ks)*32 + lane];
                mma_tf32(acc[2*p    ], A.x, A.y, A.z, A.w, B.x, B.y);
                mma_tf32(acc[2*p + 1], A.x, A.y, A.z, A.w, B.z, B.w);
            }
        }
    }
#pragma unroll
    for (int nf = 0; nf < 16; nf++) {
        int col = nf*8 + 2*cq;
        float b0 = b_out[col], b1 = b_out[col + 1];
        int mlo = mb*64 + wid*16 + r;
        *(float2*)&out[(size_t)mlo*128 + col] =
            make_float2(acc[nf][0] + b0, acc[nf][1] + b1);
        *(float2*)&out[(size_t)(mlo + 8)*128 + col] =
            make_float2(acc[nf][2] + b0, acc[nf][3] + b1);
    }
}

// ---------------- launcher -------------------------------------------------
extern "C" void kernel_launch(void* const* d_in, const int* in_sizes, int n_in,
                              void* d_out, int out_size) {
    const float* x      = (const float*)d_in[0];
    const float* gamma  = (const float*)d_in[1];
    const float* beta   = (const float*)d_in[2];
    const float* w_qkv  = (const float*)d_in[3];
    const float* w_out  = (const float*)d_in[4];
    const float* b_out  = (const float*)d_in[5];
    float* out = (float*)d_out;

    init_invf<<<1, 64>>>();
    ln_kernel<<<1024, 256>>>(x, gamma, beta);

    cudaFuncSetAttribute(qkv_kernel, cudaFuncAttributeMaxDynamicSharedMemorySize, 98304);
    qkv_kernel<<<dim3(48, 64), 256, 98304>>>(w_qkv);

    cudaFuncSetAttribute(attn_kernel, cudaFuncAttributeMaxDynamicSharedMemorySize, 65536);
    attn_kernel<<<dim3(32, 32), 128, 65536>>>();

    cudaFuncSetAttribute(outproj_kernel, cudaFuncAttributeMaxDynamicSharedMemorySize, 49152);
    outproj_kernel<<<128, 128, 49152>>>(w_out, b_out, out);
}

// round 12
// speedup vs baseline: 15.5884x; 1.2465x over previous
#include <cuda_runtime.h>
#include <cuda_fp16.h>
#include <math.h>
#include <stdint.h>

#define SEQ   2048
#define NB    4
#define NH    8
#define HD    128
#define ROWS  (NB*SEQ)          // 8192

// ---------------- scratch (all fp16 fragment-permuted) ----------------
// g_xn : fp16 A-frags per 128-row block: [wq8][ks8][lane32][4]   (8192 w/blk)
// g_q  : fp16 A-frags per (bh, 64-row block):  [w4][ks8][lane32][4] (4096 w)
// g_k  : fp16 B-frags per (bh, 64-key block):  [pair4][ks8][lane32][4] (4096 w)
// g_v  : fp16 B-frags per (bh, 64-key block):  [pair8][ks4][lane32][4] (4096 w)
// g_o  : fp16 A-frags per (64-row mblock, 64-col kchunk): [wq4][ks4][lane32][4] (2048 w)
__device__ float g_xn[ROWS*64];
__device__ float g_q[NB*NH*SEQ*HD/2 + 1024];
__device__ float g_k[NB*NH*SEQ*HD/2 + 1024];
__device__ float g_v[NB*NH*SEQ*HD/2 + 1024];
__device__ float g_o[ROWS*512 + 1024];
__device__ float g_rope[2047*128];     // [n][j] -> (cos, sin)

// ---------------- helpers ----------------
__device__ __forceinline__ uint32_t pkh2(float lo, float hi) {
    __half2 h = __floats2half2_rn(lo, hi);
    return *(uint32_t*)&h;
}
__device__ __forceinline__ void mma_f16(float* c,
        uint32_t a0, uint32_t a1, uint32_t a2, uint32_t a3,
        uint32_t b0, uint32_t b1) {
    asm volatile("mma.sync.aligned.m16n8k16.row.col.f32.f16.f16.f32 "
        "{%0,%1,%2,%3}, {%4,%5,%6,%7}, {%8,%9}, {%0,%1,%2,%3};"
        : "+f"(c[0]), "+f"(c[1]), "+f"(c[2]), "+f"(c[3])
        : "r"(a0), "r"(a1), "r"(a2), "r"(a3), "r"(b0), "r"(b1));
}
__device__ __forceinline__ float fast_ex2(float x) {
    float y;
    asm("ex2.approx.f32 %0, %1;" : "=f"(y) : "f"(x));
    return y;
}
__device__ __forceinline__ void cp_async16(uint32_t saddr, const void* gptr) {
    asm volatile("cp.async.cg.shared.global [%0], [%1], 16;"
                 :: "r"(saddr), "l"(gptr));
}

// ---------------- 0. rope table (accurate sincosf, once) -------------------
__global__ void init_rope() {
    int n = blockIdx.x;           // 0..2046
    int j = threadIdx.x;          // 0..63
    float inv = (float)pow(10000.0, -((double)(2*j) / 128.0));
    float s, c;
    sincosf((float)n * inv, &s, &c);
    g_rope[(n*64 + j)*2    ] = c;
    g_rope[(n*64 + j)*2 + 1] = s;
}

// ---------------- 1. LayerNorm -> fp16 A-frag g_xn -------------------------
__global__ void ln_kernel(const float* __restrict__ x,
                          const float* __restrict__ gamma,
                          const float* __restrict__ beta) {
    int row  = blockIdx.x * 8 + (threadIdx.x >> 5);
    int lane = threadIdx.x & 31;
    float4 v = ((const float4*)(x + (size_t)row * 128))[lane];
    float s  = v.x + v.y + v.z + v.w;
    float s2 = v.x*v.x + v.y*v.y + v.z*v.z + v.w*v.w;
#pragma unroll
    for (int m = 16; m; m >>= 1) {
        s  += __shfl_xor_sync(0xffffffffu, s,  m);
        s2 += __shfl_xor_sync(0xffffffffu, s2, m);
    }
    float mean = s * (1.f/128.f);
    float var  = s2 * (1.f/128.f) - mean*mean;
    float rs   = rsqrtf(var + 1e-5f);
    float4 g = ((const float4*)gamma)[lane];
    float4 b = ((const float4*)beta)[lane];
    float o0 = (v.x-mean)*rs*g.x + b.x;
    float o1 = (v.y-mean)*rs*g.y + b.y;
    float o2 = (v.z-mean)*rs*g.z + b.z;
    float o3 = (v.w-mean)*rs*g.w + b.w;
    // fp16 A-frag store: row rl, cols 4*lane..4*lane+3
    uint32_t* dst = (uint32_t*)g_xn + (size_t)(row >> 7)*8192;
    int rl = row & 127;
    int wq = rl >> 4, r = rl & 7, a_sel = (rl >> 3) & 1;
    int ks = lane >> 2, hi = (lane >> 1) & 1;
    int cq0 = (2*lane) & 3, cq1 = (2*lane + 1) & 3;
    dst[((wq*8 + ks)*32 + r*4 + cq0)*4 + 2*hi + a_sel] = pkh2(o0, o1);
    dst[((wq*8 + ks)*32 + r*4 + cq1)*4 + 2*hi + a_sel] = pkh2(o2, o3);
}

// ---------------- 2. QKV GEMM fp16 mma + table RoPE ------------------------
// BM=128 (8 warps x 16 rows), BN=64, K=128 (8 k-steps).
__global__ __launch_bounds__(256) void qkv_kernel(const float* __restrict__ w) {
    extern __shared__ uint32_t smu[];
    uint32_t* Ap = smu;            // 8192 w
    uint32_t* Bp = smu + 8192;     // 4096 w
    int tid = threadIdx.x, wid = tid >> 5, lane = tid & 31;
    int r = lane >> 2, cq = lane & 3;
    int n0 = blockIdx.x * 64, m0 = blockIdx.y * 128;

    // A: coalesced uint4 copy of fp16 frags
    {
        const uint4* Ag = (const uint4*)((const uint32_t*)g_xn + (size_t)blockIdx.y*8192);
        uint4* Ap4 = (uint4*)Ap;
        for (int i = tid; i < 2048; i += 256) Ap4[i] = Ag[i];
    }
    // B: pack fp16 B-frags from fp32 w
    for (int g = tid; g < 1024; g += 256) {
        int pair = g >> 8, ks = (g >> 5) & 7, lt = g & 31;
        int rr = lt >> 2, ca = lt & 3;
        const float* w0 = &w[(size_t)(n0 + pair*16 + rr)*128 + ks*16 + 2*ca];
        const float* w8 = w0 + 8*128;
        uint4 u;
        u.x = pkh2(w0[0], w0[1]);
        u.y = pkh2(w0[8], w0[9]);
        u.z = pkh2(w8[0], w8[1]);
        u.w = pkh2(w8[8], w8[9]);
        ((uint4*)Bp)[g] = u;
    }
    __syncthreads();

    float acc[8][4];
#pragma unroll
    for (int nf = 0; nf < 8; nf++)
#pragma unroll
        for (int i = 0; i < 4; i++) acc[nf][i] = 0.f;
#pragma unroll
    for (int ks = 0; ks < 8; ks++) {
        uint4 A = ((const uint4*)Ap)[(wid*8 + ks)*32 + lane];
#pragma unroll
        for (int p = 0; p < 4; p++) {
            uint4 B = ((const uint4*)Bp)[(p*8 + ks)*32 + lane];
            mma_f16(acc[2*p    ], A.x, A.y, A.z, A.w, B.x, B.y);
            mma_f16(acc[2*p + 1], A.x, A.y, A.z, A.w, B.z, B.w);
        }
    }

    // ---- epilogue: table rope (+scale*log2e for q), pack fp16 frags -------
    int part = n0 >> 10;                      // 0=q 1=k 2=v
    const float qscale = 0.08838834764831845f * 1.44269504088896340736f;
    int m_lo = m0 + wid*16 + r;
    int b_   = m_lo >> 11;
    int n_lo = m_lo & 2047;
    int n_hi = n_lo + 8;
    int bh_  = b_*8;
    int wq4  = wid & 3;
    const float2* rope2 = (const float2*)g_rope;
#pragma unroll
    for (int nf = 0; nf < 8; nf++) {
        int e = n0 + nf*8 + 2*cq;
        int h = (e & 1023) >> 7;
        int d = e & 127;
        float v0 = acc[nf][0], v1 = acc[nf][1];
        float v2 = acc[nf][2], v3 = acc[nf][3];
        if (part < 2) {
            int jj = d >> 1;
            if (n_lo < 2047) {
                float2 cs = rope2[n_lo*64 + jj];
                float t0 = v0*cs.x - v1*cs.y; v1 = v1*cs.x + v0*cs.y; v0 = t0;
            }
            if (n_hi < 2047) {
                float2 cs = rope2[n_hi*64 + jj];
                float t2 = v2*cs.x - v3*cs.y; v3 = v3*cs.x + v2*cs.y; v2 = t2;
            }
            if (part == 0) { v0*=qscale; v1*=qscale; v2*=qscale; v3*=qscale; }
        }
        int blk = (bh_ + h)*32 + (n_lo >> 6);
        int ks  = d >> 4, hi = (d >> 3) & 1;
        if (part == 0) {
            uint32_t* base = (uint32_t*)g_q + (size_t)blk*4096;
            int w0 = ((wq4*8 + ks)*32 + lane)*4 + 2*hi;
            base[w0    ] = pkh2(v0, v1);
            base[w0 + 1] = pkh2(v2, v3);
        } else if (part == 1) {
            uint32_t* base = (uint32_t*)g_k + (size_t)blk*4096;
            int w0 = ((wq4*8 + ks)*32 + lane)*4 + hi;
            base[w0    ] = pkh2(v0, v1);
            base[w0 + 2] = pkh2(v2, v3);
        } else {
            __half* base = (__half*)((uint32_t*)g_v + (size_t)blk*4096);
            int pair = d >> 4, hn = (d >> 3) & 1;
            int lane0 = 4*(d & 7) + (r >> 1);
            int w0 = ((pair*4 + wq4)*32 + lane0)*4 + 2*hn;
            int w1 = w0 + 16;
            int hf = r & 1;
            base[(w0    )*2 + hf] = __float2half(v0);
            base[(w1    )*2 + hf] = __float2half(v1);
            base[(w0 + 1)*2 + hf] = __float2half(v2);
            base[(w1 + 1)*2 + hf] = __float2half(v3);
        }
    }
}

// ---------------- 3. Flash attention fp16 mma (unchanged from R8) ----------
// smem words: K0=0, K1=4096, V0=8192, V1=12288  -> 65536 B
__global__ __launch_bounds__(128) void attn_kernel() {
    extern __shared__ uint32_t smu[];
    int tid  = threadIdx.x;
    int wid  = tid >> 5, lane = tid & 31;
    int r    = lane >> 2, cq = lane & 3;
    int bh   = blockIdx.y;

    uint4 Qf[8];
    {
        const uint4* Qg = (const uint4*)((const uint32_t*)g_q
                          + ((size_t)bh*32 + blockIdx.x)*4096);
#pragma unroll
        for (int ks = 0; ks < 8; ks++)
            Qf[ks] = Qg[(wid*8 + ks)*32 + lane];
    }

    uint32_t smem_base = (uint32_t)__cvta_generic_to_shared(smu);
    const uint32_t* Kg0 = (const uint32_t*)g_k + (size_t)bh*32*4096;
    const uint32_t* Vg0 = (const uint32_t*)g_v + (size_t)bh*32*4096;

    {
        const uint4* Kg = (const uint4*)Kg0;
        const uint4* Vg = (const uint4*)Vg0;
#pragma unroll
        for (int i = 0; i < 8; i++) {
            int idx = tid + i*128;
            cp_async16(smem_base + idx*16,          Kg + idx);
            cp_async16(smem_base + 32768 + idx*16,  Vg + idx);
        }
        asm volatile("cp.async.commit_group;" ::: "memory");
    }

    float oacc[16][4];
    float mprev0 = -INFINITY, mprev1 = -INFINITY, l0 = 0.f, l1 = 0.f;
#pragma unroll
    for (int nf = 0; nf < 16; nf++)
#pragma unroll
        for (int i = 0; i < 4; i++) oacc[nf][i] = 0.f;

    for (int t = 0; t < 32; t++) {
        int buf = t & 1;
        asm volatile("cp.async.wait_group 0;" ::: "memory");
        __syncthreads();
        if (t + 1 < 32) {
            int nb = buf ^ 1;
            const uint4* Kg = (const uint4*)(Kg0 + (size_t)(t+1)*4096);
            const uint4* Vg = (const uint4*)(Vg0 + (size_t)(t+1)*4096);
#pragma unroll
            for (int i = 0; i < 8; i++) {
                int idx = tid + i*128;
                cp_async16(smem_base + nb*16384 + idx*16,         Kg + idx);
                cp_async16(smem_base + 32768 + nb*16384 + idx*16, Vg + idx);
            }
            asm volatile("cp.async.commit_group;" ::: "memory");
        }
        const uint32_t* Kp = smu + buf*4096;
        const uint32_t* Vp = smu + 8192 + buf*4096;

        float sacc[8][4];
#pragma unroll
        for (int nf = 0; nf < 8; nf++)
#pragma unroll
            for (int i = 0; i < 4; i++) sacc[nf][i] = 0.f;
#pragma unroll
        for (int ks = 0; ks < 8; ks++) {
            uint4 A = Qf[ks];
#pragma unroll
            for (int p = 0; p < 4; p++) {
                uint4 B = ((const uint4*)Kp)[(p*8 + ks)*32 + lane];
                mma_f16(sacc[2*p    ], A.x, A.y, A.z, A.w, B.x, B.y);
                mma_f16(sacc[2*p + 1], A.x, A.y, A.z, A.w, B.z, B.w);
            }
        }

        float mx0 = -INFINITY, mx1 = -INFINITY;
#pragma unroll
        for (int nf = 0; nf < 8; nf++) {
            mx0 = fmaxf(mx0, fmaxf(sacc[nf][0], sacc[nf][1]));
            mx1 = fmaxf(mx1, fmaxf(sacc[nf][2], sacc[nf][3]));
        }
        mx0 = fmaxf(mx0, __shfl_xor_sync(0xffffffffu, mx0, 1));
        mx0 = fmaxf(mx0, __shfl_xor_sync(0xffffffffu, mx0, 2));
        mx1 = fmaxf(mx1, __shfl_xor_sync(0xffffffffu, mx1, 1));
        mx1 = fmaxf(mx1, __shfl_xor_sync(0xffffffffu, mx1, 2));
        float mn0 = fmaxf(mprev0, mx0), mn1 = fmaxf(mprev1, mx1);
        float al0 = fast_ex2(mprev0 - mn0), al1 = fast_ex2(mprev1 - mn1);
        float ps0 = 0.f, ps1 = 0.f;
        uint32_t ph[8][2];
#pragma unroll
        for (int nf = 0; nf < 8; nf++) {
            float p00 = fast_ex2(sacc[nf][0] - mn0);
            float p01 = fast_ex2(sacc[nf][1] - mn0);
            float p10 = fast_ex2(sacc[nf][2] - mn1);
            float p11 = fast_ex2(sacc[nf][3] - mn1);
            ps0 += p00 + p01;  ps1 += p10 + p11;
            ph[nf][0] = pkh2(p00, p01);
            ph[nf][1] = pkh2(p10, p11);
        }
        ps0 += __shfl_xor_sync(0xffffffffu, ps0, 1);
        ps0 += __shfl_xor_sync(0xffffffffu, ps0, 2);
        ps1 += __shfl_xor_sync(0xffffffffu, ps1, 1);
        ps1 += __shfl_xor_sync(0xffffffffu, ps1, 2);
        l0 = l0*al0 + ps0;  l1 = l1*al1 + ps1;
        mprev0 = mn0;       mprev1 = mn1;
#pragma unroll
        for (int nf = 0; nf < 16; nf++) {
            oacc[nf][0] *= al0; oacc[nf][1] *= al0;
            oacc[nf][2] *= al1; oacc[nf][3] *= al1;
        }

#pragma unroll
        for (int ks = 0; ks < 4; ks++) {
            uint32_t a0 = ph[2*ks    ][0];
            uint32_t a1 = ph[2*ks    ][1];
            uint32_t a2 = ph[2*ks + 1][0];
            uint32_t a3 = ph[2*ks + 1][1];
#pragma unroll
            for (int p = 0; p < 8; p++) {
                uint4 B = ((const uint4*)Vp)[(p*4 + ks)*32 + lane];
                mma_f16(oacc[2*p    ], a0, a1, a2, a3, B.x, B.y);
                mma_f16(oacc[2*p + 1], a0, a1, a2, a3, B.z, B.w);
            }
        }
    }
    // ---- epilogue: write fp16 A-frags to g_o (for outproj) ----
    float inv0 = 1.f / l0, inv1 = 1.f / l1;
    int b  = bh >> 3, h = bh & 7;
    int mb = b*32 + blockIdx.x;
    uint32_t* OG = (uint32_t*)g_o;
#pragma unroll
    for (int nf = 0; nf < 16; nf++) {
        int d  = nf*8 + 2*cq;
        int kc = h*2 + (d >> 6);
        int kk = d & 63;
        int ks = kk >> 4, hi = (kk >> 3) & 1;
        size_t base = ((size_t)mb*16 + kc)*2048;
        int w0 = ((wid*4 + ks)*32 + r*4 + cq)*4 + 2*hi;
        OG[base + w0    ] = pkh2(oacc[nf][0]*inv0, oacc[nf][1]*inv0);
        OG[base + w0 + 1] = pkh2(oacc[nf][2]*inv1, oacc[nf][3]*inv1);
    }
}

// ---------------- 4. Out projection, fp16 mma ------------------------------
// BM=64 (4 warps), N=128, K=1024 in 16 chunks of 64 (4 k-steps each).
__global__ __launch_bounds__(128) void outproj_kernel(const float* __restrict__ w_out,
                                                      const float* __restrict__ b_out,
                                                      float* __restrict__ out) {
    extern __shared__ uint32_t smu[];
    uint32_t* Ap = smu;           // 2048 w
    uint32_t* Bp = smu + 2048;    // 4096 w
    int tid = threadIdx.x, wid = tid >> 5, lane = tid & 31;
    int r = lane >> 2, cq = lane & 3;
    int mb = blockIdx.x;

    float acc[16][4];
#pragma unroll
    for (int nf = 0; nf < 16; nf++)
#pragma unroll
        for (int i = 0; i < 4; i++) acc[nf][i] = 0.f;

    for (int kc = 0; kc < 16; kc++) {
        __syncthreads();
        {
            const uint4* Ag = (const uint4*)((const uint32_t*)g_o
                              + ((size_t)mb*16 + kc)*2048);
            uint4* Ap4 = (uint4*)Ap;
            for (int i = tid; i < 512; i += 128) Ap4[i] = Ag[i];
        }
        for (int g = tid; g < 1024; g += 128) {
            int pair = g >> 7, ks = (g >> 5) & 3, lt = g & 31;
            int rr = lt >> 2, ca = lt & 3;
            const float* p0 = &w_out[(size_t)(pair*16 + rr)*1024 + kc*64 + ks*16 + 2*ca];
            const float* p8 = p0 + 8*1024;
            uint4 u;
            u.x = pkh2(p0[0], p0[1]);
            u.y = pkh2(p0[8], p0[9]);
            u.z = pkh2(p8[0], p8[1]);
            u.w = pkh2(p8[8], p8[9]);
            ((uint4*)Bp)[g] = u;
        }
        __syncthreads();
#pragma unroll
        for (int ks = 0; ks < 4; ks++) {
            uint4 A = ((const uint4*)Ap)[(wid*4 + ks)*32 + lane];
#pragma unroll
            for (int p = 0; p < 8; p++) {
                uint4 B = ((const uint4*)Bp)[(p*4 + ks)*32 + lane];
                mma_f16(acc[2*p    ], A.x, A.y, A.z, A.w, B.x, B.y);
                mma_f16(acc[2*p + 1], A.x, A.y, A.z, A.w, B.z, B.w);
            }
        }
    }
#pragma unroll
    for (int nf = 0; nf < 16; nf++) {
        int col = nf*8 + 2*cq;
        float b0 = b_out[col], b1 = b_out[col + 1];
        int mlo = mb*64 + wid*16 + r;
        *(float2*)&out[(size_t)mlo*128 + col] =
            make_float2(acc[nf][0] + b0, acc[nf][1] + b1);
        *(float2*)&out[(size_t)(mlo + 8)*128 + col] =
            make_float2(acc[nf][2] + b0, acc[nf][3] + b1);
    }
}

// ---------------- launcher -------------------------------------------------
extern "C" void kernel_launch(void* const* d_in, const int* in_sizes, int n_in,
                              void* d_out, int out_size) {
    const float* x      = (const float*)d_in[0];
    const float* gamma  = (const float*)d_in[1];
    const float* beta   = (const float*)d_in[2];
    const float* w_qkv  = (const float*)d_in[3];
    const float* w_out  = (const float*)d_in[4];
    const float* b_out  = (const float*)d_in[5];
    float* out = (float*)d_out;

    init_rope<<<2047, 64>>>();
    ln_kernel<<<1024, 256>>>(x, gamma, beta);

    cudaFuncSetAttribute(qkv_kernel, cudaFuncAttributeMaxDynamicSharedMemorySize, 49152);
    qkv_kernel<<<dim3(48, 64), 256, 49152>>>(w_qkv);

    cudaFuncSetAttribute(attn_kernel, cudaFuncAttributeMaxDynamicSharedMemorySize, 65536);
    attn_kernel<<<dim3(32, 32), 128, 65536>>>();

    cudaFuncSetAttribute(outproj_kernel, cudaFuncAttributeMaxDynamicSharedMemorySize, 24576);
    outproj_kernel<<<128, 128, 24576>>>(w_out, b_out, out);
}

// round 14
// speedup vs baseline: 17.4816x; 1.1214x over previous
#include <cuda_runtime.h>
#include <cuda_fp16.h>
#include <math.h>
#include <stdint.h>

#define SEQ   2048
#define NB    4
#define NH    8
#define HD    128
#define ROWS  (NB*SEQ)          // 8192

// ---------------- scratch (all fp16 fragment-permuted) ----------------
// g_xn : fp16 A-frags per 128-row block: [wq8][ks8][lane32][4]   (8192 w/blk)
// g_q  : fp16 A-frags per (bh, 64-row block):  [w4][ks8][lane32][4] (4096 w)
// g_k  : fp16 B-frags per (bh, 64-key block):  [pair4][ks8][lane32][4] (4096 w)
// g_v  : fp16 B-frags per (bh, 64-key block):  [pair8][ks4][lane32][4] (4096 w)
// g_o  : fp16 A-frags per (64-row mblock, 64-col kchunk): [wq4][ks4][lane32][4] (2048 w)
__device__ float g_xn[ROWS*64];
__device__ float g_q[NB*NH*SEQ*HD/2 + 1024];
__device__ float g_k[NB*NH*SEQ*HD/2 + 1024];
__device__ float g_v[NB*NH*SEQ*HD/2 + 1024];
__device__ float g_o[ROWS*512 + 1024];
__device__ float g_rope[2047*128];     // [n][j] -> (cos, sin)

// ---------------- helpers ----------------
__device__ __forceinline__ uint32_t pkh2(float lo, float hi) {
    __half2 h = __floats2half2_rn(lo, hi);
    return *(uint32_t*)&h;
}
__device__ __forceinline__ void mma_f16(float* c,
        uint32_t a0, uint32_t a1, uint32_t a2, uint32_t a3,
        uint32_t b0, uint32_t b1) {
    asm volatile("mma.sync.aligned.m16n8k16.row.col.f32.f16.f16.f32 "
        "{%0,%1,%2,%3}, {%4,%5,%6,%7}, {%8,%9}, {%0,%1,%2,%3};"
        : "+f"(c[0]), "+f"(c[1]), "+f"(c[2]), "+f"(c[3])
        : "r"(a0), "r"(a1), "r"(a2), "r"(a3), "r"(b0), "r"(b1));
}
__device__ __forceinline__ float fast_ex2(float x) {
    float y;
    asm("ex2.approx.f32 %0, %1;" : "=f"(y) : "f"(x));
    return y;
}
__device__ __forceinline__ void cp_async16(uint32_t saddr, const void* gptr) {
    asm volatile("cp.async.cg.shared.global [%0], [%1], 16;"
                 :: "r"(saddr), "l"(gptr));
}

// ---------------- 0. rope table (accurate sincosf, once per launch) --------
__global__ void init_rope() {
    int n = blockIdx.x;           // 0..2046
    int j = threadIdx.x;          // 0..63
    float inv = (float)pow(10000.0, -((double)(2*j) / 128.0));
    float s, c;
    sincosf((float)n * inv, &s, &c);
    g_rope[(n*64 + j)*2    ] = c;
    g_rope[(n*64 + j)*2 + 1] = s;
}

// ---------------- 1. LayerNorm -> fp16 A-frag g_xn -------------------------
__global__ void ln_kernel(const float* __restrict__ x,
                          const float* __restrict__ gamma,
                          const float* __restrict__ beta) {
    int row  = blockIdx.x * 8 + (threadIdx.x >> 5);
    int lane = threadIdx.x & 31;
    float4 v = ((const float4*)(x + (size_t)row * 128))[lane];
    float s  = v.x + v.y + v.z + v.w;
    float s2 = v.x*v.x + v.y*v.y + v.z*v.z + v.w*v.w;
#pragma unroll
    for (int m = 16; m; m >>= 1) {
        s  += __shfl_xor_sync(0xffffffffu, s,  m);
        s2 += __shfl_xor_sync(0xffffffffu, s2, m);
    }
    float mean = s * (1.f/128.f);
    float var  = s2 * (1.f/128.f) - mean*mean;
    float rs   = rsqrtf(var + 1e-5f);
    float4 g = ((const float4*)gamma)[lane];
    float4 b = ((const float4*)beta)[lane];
    float o0 = (v.x-mean)*rs*g.x + b.x;
    float o1 = (v.y-mean)*rs*g.y + b.y;
    float o2 = (v.z-mean)*rs*g.z + b.z;
    float o3 = (v.w-mean)*rs*g.w + b.w;
    uint32_t* dst = (uint32_t*)g_xn + (size_t)(row >> 7)*8192;
    int rl = row & 127;
    int wq = rl >> 4, r = rl & 7, a_sel = (rl >> 3) & 1;
    int ks = lane >> 2, hi = (lane >> 1) & 1;
    int cq0 = (2*lane) & 3, cq1 = (2*lane + 1) & 3;
    dst[((wq*8 + ks)*32 + r*4 + cq0)*4 + 2*hi + a_sel] = pkh2(o0, o1);
    dst[((wq*8 + ks)*32 + r*4 + cq1)*4 + 2*hi + a_sel] = pkh2(o2, o3);
}

// ---------------- 2. QKV GEMM fp16 mma + table RoPE, BN=128 ----------------
// BM=128 (8 warps x 16 rows), BN=128, K=128 (8 k-steps). grid (24, 64).
__global__ __launch_bounds__(256) void qkv_kernel(const float* __restrict__ w) {
    extern __shared__ uint32_t smu[];
    uint32_t* Ap = smu;            // 8192 w
    uint32_t* Bp = smu + 8192;     // 8192 w
    int tid = threadIdx.x, wid = tid >> 5, lane = tid & 31;
    int r = lane >> 2, cq = lane & 3;
    int n0 = blockIdx.x * 128, m0 = blockIdx.y * 128;

    // A: cp.async pure copy of fp16 frags (2048 uint4)
    uint32_t smem_base = (uint32_t)__cvta_generic_to_shared(smu);
    {
        const uint4* Ag = (const uint4*)((const uint32_t*)g_xn + (size_t)blockIdx.y*8192);
#pragma unroll
        for (int i = 0; i < 8; i++) {
            int idx = tid + i*256;
            cp_async16(smem_base + idx*16, Ag + idx);
        }
        asm volatile("cp.async.commit_group;" ::: "memory");
    }
    // B: pack fp16 B-frags from fp32 w (8 pairs x 8 ks x 32)
    for (int g = tid; g < 2048; g += 256) {
        int pair = g >> 8, ks = (g >> 5) & 7, lt = g & 31;
        int rr = lt >> 2, ca = lt & 3;
        const float* w0p = &w[(size_t)(n0 + pair*16 + rr)*128 + ks*16 + 2*ca];
        const float* w8p = w0p + 8*128;
        uint4 u;
        u.x = pkh2(w0p[0], w0p[1]);
        u.y = pkh2(w0p[8], w0p[9]);
        u.z = pkh2(w8p[0], w8p[1]);
        u.w = pkh2(w8p[8], w8p[9]);
        ((uint4*)Bp)[g] = u;
    }
    asm volatile("cp.async.wait_group 0;" ::: "memory");
    __syncthreads();

    float acc[16][4];
#pragma unroll
    for (int nf = 0; nf < 16; nf++)
#pragma unroll
        for (int i = 0; i < 4; i++) acc[nf][i] = 0.f;
#pragma unroll
    for (int ks = 0; ks < 8; ks++) {
        uint4 A = ((const uint4*)Ap)[(wid*8 + ks)*32 + lane];
#pragma unroll
        for (int p = 0; p < 8; p++) {
            uint4 B = ((const uint4*)Bp)[(p*8 + ks)*32 + lane];
            mma_f16(acc[2*p    ], A.x, A.y, A.z, A.w, B.x, B.y);
            mma_f16(acc[2*p + 1], A.x, A.y, A.z, A.w, B.z, B.w);
        }
    }

    // ---- epilogue: table rope (+scale*log2e for q), pack fp16 frags -------
    int part = n0 >> 10;                      // constant per CTA (n0 mult of 128)
    const float qscale = 0.08838834764831845f * 1.44269504088896340736f;
    int m_lo = m0 + wid*16 + r;
    int b_   = m_lo >> 11;
    int n_lo = m_lo & 2047;
    int n_hi = n_lo + 8;
    int bh_  = b_*8;
    int wq4  = wid & 3;
    const float2* rope2 = (const float2*)g_rope;
#pragma unroll
    for (int nf = 0; nf < 16; nf++) {
        int e = n0 + nf*8 + 2*cq;
        int h = (e & 1023) >> 7;
        int d = e & 127;
        float v0 = acc[nf][0], v1 = acc[nf][1];
        float v2 = acc[nf][2], v3 = acc[nf][3];
        if (part < 2) {
            int jj = d >> 1;
            if (n_lo < 2047) {
                float2 cs = rope2[n_lo*64 + jj];
                float t0 = v0*cs.x - v1*cs.y; v1 = v1*cs.x + v0*cs.y; v0 = t0;
            }
            if (n_hi < 2047) {
                float2 cs = rope2[n_hi*64 + jj];
                float t2 = v2*cs.x - v3*cs.y; v3 = v3*cs.x + v2*cs.y; v2 = t2;
            }
            if (part == 0) { v0*=qscale; v1*=qscale; v2*=qscale; v3*=qscale; }
        }
        int blk = (bh_ + h)*32 + (n_lo >> 6);
        int ks  = d >> 4, hi = (d >> 3) & 1;
        if (part == 0) {
            uint32_t* base = (uint32_t*)g_q + (size_t)blk*4096;
            int w0 = ((wq4*8 + ks)*32 + lane)*4 + 2*hi;
            base[w0    ] = pkh2(v0, v1);
            base[w0 + 1] = pkh2(v2, v3);
        } else if (part == 1) {
            uint32_t* base = (uint32_t*)g_k + (size_t)blk*4096;
            int w0 = ((wq4*8 + ks)*32 + lane)*4 + hi;
            base[w0    ] = pkh2(v0, v1);
            base[w0 + 2] = pkh2(v2, v3);
        } else {
            __half* base = (__half*)((uint32_t*)g_v + (size_t)blk*4096);
            int pair = d >> 4, hn = (d >> 3) & 1;
            int lane0 = 4*(d & 7) + (r >> 1);
            int w0 = ((pair*4 + wq4)*32 + lane0)*4 + 2*hn;
            int w1 = w0 + 16;
            int hf = r & 1;
            base[(w0    )*2 + hf] = __float2half(v0);
            base[(w1    )*2 + hf] = __float2half(v1);
            base[(w0 + 1)*2 + hf] = __float2half(v2);
            base[(w1 + 1)*2 + hf] = __float2half(v3);
        }
    }
}

// ---------------- 3. Flash attention fp16 mma (unchanged, measured 179us) --
// smem words: K0=0, K1=4096, V0=8192, V1=12288  -> 65536 B
__global__ __launch_bounds__(128) void attn_kernel() {
    extern __shared__ uint32_t smu[];
    int tid  = threadIdx.x;
    int wid  = tid >> 5, lane = tid & 31;
    int r    = lane >> 2, cq = lane & 3;
    int bh   = blockIdx.y;

    uint4 Qf[8];
    {
        const uint4* Qg = (const uint4*)((const uint32_t*)g_q
                          + ((size_t)bh*32 + blockIdx.x)*4096);
#pragma unroll
        for (int ks = 0; ks < 8; ks++)
            Qf[ks] = Qg[(wid*8 + ks)*32 + lane];
    }

    uint32_t smem_base = (uint32_t)__cvta_generic_to_shared(smu);
    const uint32_t* Kg0 = (const uint32_t*)g_k + (size_t)bh*32*4096;
    const uint32_t* Vg0 = (const uint32_t*)g_v + (size_t)bh*32*4096;

    {
        const uint4* Kg = (const uint4*)Kg0;
        const uint4* Vg = (const uint4*)Vg0;
#pragma unroll
        for (int i = 0; i < 8; i++) {
            int idx = tid + i*128;
            cp_async16(smem_base + idx*16,          Kg + idx);
            cp_async16(smem_base + 32768 + idx*16,  Vg + idx);
        }
        asm volatile("cp.async.commit_group;" ::: "memory");
    }

    float oacc[16][4];
    float mprev0 = -INFINITY, mprev1 = -INFINITY, l0 = 0.f, l1 = 0.f;
#pragma unroll
    for (int nf = 0; nf < 16; nf++)
#pragma unroll
        for (int i = 0; i < 4; i++) oacc[nf][i] = 0.f;

    for (int t = 0; t < 32; t++) {
        int buf = t & 1;
        asm volatile("cp.async.wait_group 0;" ::: "memory");
        __syncthreads();
        if (t + 1 < 32) {
            int nb = buf ^ 1;
            const uint4* Kg = (const uint4*)(Kg0 + (size_t)(t+1)*4096);
            const uint4* Vg = (const uint4*)(Vg0 + (size_t)(t+1)*4096);
#pragma unroll
            for (int i = 0; i < 8; i++) {
                int idx = tid + i*128;
                cp_async16(smem_base + nb*16384 + idx*16,         Kg + idx);
                cp_async16(smem_base + 32768 + nb*16384 + idx*16, Vg + idx);
            }
            asm volatile("cp.async.commit_group;" ::: "memory");
        }
        const uint32_t* Kp = smu + buf*4096;
        const uint32_t* Vp = smu + 8192 + buf*4096;

        float sacc[8][4];
#pragma unroll
        for (int nf = 0; nf < 8; nf++)
#pragma unroll
            for (int i = 0; i < 4; i++) sacc[nf][i] = 0.f;
#pragma unroll
        for (int ks = 0; ks < 8; ks++) {
            uint4 A = Qf[ks];
#pragma unroll
            for (int p = 0; p < 4; p++) {
                uint4 B = ((const uint4*)Kp)[(p*8 + ks)*32 + lane];
                mma_f16(sacc[2*p    ], A.x, A.y, A.z, A.w, B.x, B.y);
                mma_f16(sacc[2*p + 1], A.x, A.y, A.z, A.w, B.z, B.w);
            }
        }

        float mx0 = -INFINITY, mx1 = -INFINITY;
#pragma unroll
        for (int nf = 0; nf < 8; nf++) {
            mx0 = fmaxf(mx0, fmaxf(sacc[nf][0], sacc[nf][1]));
            mx1 = fmaxf(mx1, fmaxf(sacc[nf][2], sacc[nf][3]));
        }
        mx0 = fmaxf(mx0, __shfl_xor_sync(0xffffffffu, mx0, 1));
        mx0 = fmaxf(mx0, __shfl_xor_sync(0xffffffffu, mx0, 2));
        mx1 = fmaxf(mx1, __shfl_xor_sync(0xffffffffu, mx1, 1));
        mx1 = fmaxf(mx1, __shfl_xor_sync(0xffffffffu, mx1, 2));
        float mn0 = fmaxf(mprev0, mx0), mn1 = fmaxf(mprev1, mx1);
        float al0 = fast_ex2(mprev0 - mn0), al1 = fast_ex2(mprev1 - mn1);
        float ps0 = 0.f, ps1 = 0.f;
        uint32_t ph[8][2];
#pragma unroll
        for (int nf = 0; nf < 8; nf++) {
            float p00 = fast_ex2(sacc[nf][0] - mn0);
            float p01 = fast_ex2(sacc[nf][1] - mn0);
            float p10 = fast_ex2(sacc[nf][2] - mn1);
            float p11 = fast_ex2(sacc[nf][3] - mn1);
            ps0 += p00 + p01;  ps1 += p10 + p11;
            ph[nf][0] = pkh2(p00, p01);
            ph[nf][1] = pkh2(p10, p11);
        }
        ps0 += __shfl_xor_sync(0xffffffffu, ps0, 1);
        ps0 += __shfl_xor_sync(0xffffffffu, ps0, 2);
        ps1 += __shfl_xor_sync(0xffffffffu, ps1, 1);
        ps1 += __shfl_xor_sync(0xffffffffu, ps1, 2);
        l0 = l0*al0 + ps0;  l1 = l1*al1 + ps1;
        mprev0 = mn0;       mprev1 = mn1;
#pragma unroll
        for (int nf = 0; nf < 16; nf++) {
            oacc[nf][0] *= al0; oacc[nf][1] *= al0;
            oacc[nf][2] *= al1; oacc[nf][3] *= al1;
        }

#pragma unroll
        for (int ks = 0; ks < 4; ks++) {
            uint32_t a0 = ph[2*ks    ][0];
            uint32_t a1 = ph[2*ks    ][1];
            uint32_t a2 = ph[2*ks + 1][0];
            uint32_t a3 = ph[2*ks + 1][1];
#pragma unroll
            for (int p = 0; p < 8; p++) {
                uint4 B = ((const uint4*)Vp)[(p*4 + ks)*32 + lane];
                mma_f16(oacc[2*p    ], a0, a1, a2, a3, B.x, B.y);
                mma_f16(oacc[2*p + 1], a0, a1, a2, a3, B.z, B.w);
            }
        }
    }
    // ---- epilogue: write fp16 A-frags to g_o (for outproj) ----
    float inv0 = 1.f / l0, inv1 = 1.f / l1;
    int b  = bh >> 3, h = bh & 7;
    int mb = b*32 + blockIdx.x;
    uint32_t* OG = (uint32_t*)g_o;
#pragma unroll
    for (int nf = 0; nf < 16; nf++) {
        int d  = nf*8 + 2*cq;
        int kc = h*2 + (d >> 6);
        int kk = d & 63;
        int ks = kk >> 4, hi = (kk >> 3) & 1;
        size_t base = ((size_t)mb*16 + kc)*2048;
        int w0 = ((wid*4 + ks)*32 + r*4 + cq)*4 + 2*hi;
        OG[base + w0    ] = pkh2(oacc[nf][0]*inv0, oacc[nf][1]*inv0);
        OG[base + w0 + 1] = pkh2(oacc[nf][2]*inv1, oacc[nf][3]*inv1);
    }
}

// ---------------- 4. Out projection fp16 mma, N-split, K-chunks of 128 -----
// BM=64 (4 warps), BN=64 per CTA, grid (128, 2). 8 K-chunks of 128.
__global__ __launch_bounds__(128) void outproj_kernel(const float* __restrict__ w_out,
                                                      const float* __restrict__ b_out,
                                                      float* __restrict__ out) {
    extern __shared__ uint32_t smu[];
    uint32_t* Ap = smu;           // 4096 w (16KB)
    uint32_t* Bp = smu + 4096;    // 4096 w (16KB)
    int tid = threadIdx.x, wid = tid >> 5, lane = tid & 31;
    int r = lane >> 2, cq = lane & 3;
    int mb = blockIdx.x;
    int nb = blockIdx.y * 64;
    uint32_t smem_base = (uint32_t)__cvta_generic_to_shared(smu);

    float acc[8][4];
#pragma unroll
    for (int nf = 0; nf < 8; nf++)
#pragma unroll
        for (int i = 0; i < 4; i++) acc[nf][i] = 0.f;

    for (int kc = 0; kc < 8; kc++) {
        __syncthreads();
        // A: 1024 uint4 cp.async (two consecutive g_o 2048-word blocks)
        {
            const uint4* Ag = (const uint4*)((const uint32_t*)g_o
                              + ((size_t)mb*16 + kc*2)*2048);
#pragma unroll
            for (int i = 0; i < 8; i++) {
                int idx = tid + i*128;
                cp_async16(smem_base + idx*16, Ag + idx);
            }
            asm volatile("cp.async.commit_group;" ::: "memory");
        }
        // B: pack 1024 uint4 (4 pairs x 8 ks x 32)
        for (int g = tid; g < 1024; g += 128) {
            int pair = g >> 8, ks = (g >> 5) & 7, lt = g & 31;
            int rr = lt >> 2, ca = lt & 3;
            const float* p0 = &w_out[(size_t)(nb + pair*16 + rr)*1024 + kc*128 + ks*16 + 2*ca];
            const float* p8 = p0 + 8*1024;
            uint4 u;
            u.x = pkh2(p0[0], p0[1]);
            u.y = pkh2(p0[8], p0[9]);
            u.z = pkh2(p8[0], p8[1]);
            u.w = pkh2(p8[8], p8[9]);
            ((uint4*)Bp)[g] = u;
        }
        asm volatile("cp.async.wait_group 0;" ::: "memory");
        __syncthreads();
#pragma unroll
        for (int ks = 0; ks < 8; ks++) {
            uint4 A = ((const uint4*)Ap)[(ks >> 2)*512 + (wid*4 + (ks & 3))*32 + lane];
#pragma unroll
            for (int p = 0; p < 4; p++) {
                uint4 B = ((const uint4*)Bp)[(p*8 + ks)*32 + lane];
                mma_f16(acc[2*p    ], A.x, A.y, A.z, A.w, B.x, B.y);
                mma_f16(acc[2*p + 1], A.x, A.y, A.z, A.w, B.z, B.w);
            }
        }
    }
#pragma unroll
    for (int nf = 0; nf < 8; nf++) {
        int col = nb + nf*8 + 2*cq;
        float b0 = b_out[col], b1 = b_out[col + 1];
        int mlo = mb*64 + wid*16 + r;
        *(float2*)&out[(size_t)mlo*128 + col] =
            make_float2(acc[nf][0] + b0, acc[nf][1] + b1);
        *(float2*)&out[(size_t)(mlo + 8)*128 + col] =
            make_float2(acc[nf][2] + b0, acc[nf][3] + b1);
    }
}

// ---------------- launcher -------------------------------------------------
extern "C" void kernel_launch(void* const* d_in, const int* in_sizes, int n_in,
                              void* d_out, int out_size) {
    const float* x      = (const float*)d_in[0];
    const float* gamma  = (const float*)d_in[1];
    const float* beta   = (const float*)d_in[2];
    const float* w_qkv  = (const float*)d_in[3];
    const float* w_out  = (const float*)d_in[4];
    const float* b_out  = (const float*)d_in[5];
    float* out = (float*)d_out;

    init_rope<<<2047, 64>>>();
    ln_kernel<<<1024, 256>>>(x, gamma, beta);

    cudaFuncSetAttribute(qkv_kernel, cudaFuncAttributeMaxDynamicSharedMemorySize, 65536);
    qkv_kernel<<<dim3(24, 64), 256, 65536>>>(w_qkv);

    cudaFuncSetAttribute(attn_kernel, cudaFuncAttributeMaxDynamicSharedMemorySize, 65536);
    attn_kernel<<<dim3(32, 32), 128, 65536>>>();

    cudaFuncSetAttribute(outproj_kernel, cudaFuncAttributeMaxDynamicSharedMemorySize, 32768);
    outproj_kernel<<<dim3(128, 2), 128, 32768>>>(w_out, b_out, out);
}